// round 1
// baseline (speedup 1.0000x reference)
#include <cuda_runtime.h>
#include <float.h>

#define ALPHA 0.2f

// ---------------- static device scratch (no runtime allocation) ----------------
__device__ __align__(16) float g_Wt[512 * 256];           // W transposed [IN_F, OUT_F]
__device__ __align__(16) float g_Wh[8192 * 256];          // Wh [N, OUT_F]
__device__ __align__(16) float g_ssrc[8192];
__device__ __align__(16) float g_sdst[8192];
// Fallback attention buffer in case d_out only holds h_prime (expected unused:
// reference returns (h_prime, attention) concatenated).
__device__ __align__(16) float g_attn_fb[67108864];       // 8192*8192

// ---------------- W transpose: Wt[k*OUTF + n] = W[n*INF + k] ----------------
__global__ void transpose_w(const float* __restrict__ W, float* __restrict__ Wt,
                            int INF, int OUTF) {
    int idx = blockIdx.x * blockDim.x + threadIdx.x;
    if (idx >= INF * OUTF) return;
    int k = idx / OUTF;
    int n = idx - k * OUTF;
    Wt[idx] = W[n * INF + k];
}

// ---------------- fp32 SIMT GEMM: C[M,N] = A[M,K] @ B[K,N] ----------------
// BM=128, BN=64, BK=16, 256 threads, 8x4 per-thread microtile.
// Requires M%128==0, N%64==0, K%16==0 (true for this problem).
__global__ __launch_bounds__(256)
void sgemm128x64(const float* __restrict__ A, const float* __restrict__ B,
                 float* __restrict__ C, int M, int N, int K) {
    const int BM = 128, BN = 64, BK = 16;
    __shared__ float As[BK][BM];   // transposed A tile
    __shared__ float Bs[BK][BN];

    int tid = threadIdx.x;
    int tx = tid & 15;             // 0..15 -> N direction (x4)
    int ty = tid >> 4;             // 0..15 -> M direction (x8)
    int rowBase = blockIdx.y * BM;
    int colBase = blockIdx.x * BN;

    float acc[8][4];
#pragma unroll
    for (int i = 0; i < 8; i++)
#pragma unroll
        for (int j = 0; j < 4; j++) acc[i][j] = 0.0f;

    // B-tile load indices: 16x64 = 256 float4, one per thread
    int br = tid >> 4;             // 0..15
    int bc = (tid & 15) * 4;       // 0..60

    for (int kt = 0; kt < K; kt += BK) {
        // Load A tile 128x16 (2 float4 per thread), store transposed
#pragma unroll
        for (int l = 0; l < 2; l++) {
            int v  = tid + l * 256;        // float4 id 0..511
            int ar = v >> 2;               // row 0..127
            int ac = (v & 3) * 4;          // col 0,4,8,12
            const float4 t = *(const float4*)&A[(size_t)(rowBase + ar) * K + kt + ac];
            As[ac + 0][ar] = t.x;
            As[ac + 1][ar] = t.y;
            As[ac + 2][ar] = t.z;
            As[ac + 3][ar] = t.w;
        }
        // Load B tile 16x64
        *(float4*)&Bs[br][bc] = *(const float4*)&B[(size_t)(kt + br) * N + colBase + bc];
        __syncthreads();

#pragma unroll
        for (int kk = 0; kk < BK; kk++) {
            float a0[4], a1[4], b[4];
            *(float4*)a0 = *(const float4*)&As[kk][ty * 8];
            *(float4*)a1 = *(const float4*)&As[kk][ty * 8 + 4];
            *(float4*)b  = *(const float4*)&Bs[kk][tx * 4];
#pragma unroll
            for (int i = 0; i < 4; i++)
#pragma unroll
                for (int j = 0; j < 4; j++) {
                    acc[i][j]     += a0[i] * b[j];
                    acc[4 + i][j] += a1[i] * b[j];
                }
        }
        __syncthreads();
    }

#pragma unroll
    for (int i = 0; i < 8; i++) {
        float4 r = make_float4(acc[i][0], acc[i][1], acc[i][2], acc[i][3]);
        *(float4*)&C[(size_t)(rowBase + ty * 8 + i) * N + colBase + tx * 4] = r;
    }
}

// ---------------- s_src / s_dst: per-row dot products with a_vec halves ----------------
__global__ void compute_s(const float* __restrict__ Wh, const float* __restrict__ a_vec,
                          float* __restrict__ ssrc, float* __restrict__ sdst, int OUTF) {
    int i = blockIdx.x;
    int tid = threadIdx.x;
    float p1 = 0.0f, p2 = 0.0f;
    for (int j = tid; j < OUTF; j += blockDim.x) {
        float v = Wh[(size_t)i * OUTF + j];
        p1 += v * a_vec[j];
        p2 += v * a_vec[OUTF + j];
    }
#pragma unroll
    for (int off = 16; off > 0; off >>= 1) {
        p1 += __shfl_down_sync(0xffffffffu, p1, off);
        p2 += __shfl_down_sync(0xffffffffu, p2, off);
    }
    __shared__ float r1[8], r2[8];
    int wid = tid >> 5;
    if ((tid & 31) == 0) { r1[wid] = p1; r2[wid] = p2; }
    __syncthreads();
    if (tid == 0) {
        float s1 = 0.0f, s2 = 0.0f;
        int nw = blockDim.x >> 5;
        for (int w = 0; w < nw; w++) { s1 += r1[w]; s2 += r2[w]; }
        ssrc[i] = s1;
        sdst[i] = s2;
    }
}

// ---------------- masked row softmax: attention[i, :] ----------------
// One block per row. adj row cached in dynamic smem (N floats).
__global__ void attn_softmax(const float* __restrict__ adj, const float* __restrict__ sdst,
                             const float* __restrict__ ssrc, float* __restrict__ attn,
                             int Nn) {
    extern __shared__ float sh[];          // [Nn] row buffer, then red[]
    float* red = sh + Nn;
    int i   = blockIdx.x;
    int tid = threadIdx.x;
    int T   = blockDim.x;
    int n4  = Nn >> 2;

    const float4* adj4 = (const float4*)(adj + (size_t)i * Nn);
    const float4* sd4  = (const float4*)sdst;
    float4* sh4        = (float4*)sh;
    float si = ssrc[i];

    // Pass 1: cache adj row, masked max of s_dst
    float m = -FLT_MAX;
    for (int v = tid; v < n4; v += T) {
        float4 a = adj4[v];
        float4 s = sd4[v];
        sh4[v] = a;
        if (a.x > 0.0f) m = fmaxf(m, s.x);
        if (a.y > 0.0f) m = fmaxf(m, s.y);
        if (a.z > 0.0f) m = fmaxf(m, s.z);
        if (a.w > 0.0f) m = fmaxf(m, s.w);
    }
#pragma unroll
    for (int off = 16; off > 0; off >>= 1)
        m = fmaxf(m, __shfl_down_sync(0xffffffffu, m, off));
    if ((tid & 31) == 0) red[tid >> 5] = m;
    __syncthreads();
    if (tid == 0) {
        float mm = red[0];
        int nw = T >> 5;
        for (int w = 1; w < nw; w++) mm = fmaxf(mm, red[w]);
        red[32] = mm;
    }
    __syncthreads();
    float mAll = red[32];

    float4* out4 = (float4*)(attn + (size_t)i * Nn);

    if (mAll == -FLT_MAX) {
        // No neighbors: softmax over all NEG_INF -> uniform
        float u = 1.0f / (float)Nn;
        float4 uv = make_float4(u, u, u, u);
        for (int v = tid; v < n4; v += T) out4[v] = uv;
        return;
    }

    float t0 = si + mAll;
    float emax = (t0 > 0.0f) ? t0 : ALPHA * t0;

    // Pass 2: probabilities into smem, partial sum
    float sum = 0.0f;
    for (int v = tid; v < n4; v += T) {
        float4 a = sh4[v];
        float4 s = sd4[v];
        float4 p;
        float x;
        x   = si + s.x; x = (x > 0.0f) ? x : ALPHA * x;
        p.x = (a.x > 0.0f) ? __expf(x - emax) : 0.0f;
        x   = si + s.y; x = (x > 0.0f) ? x : ALPHA * x;
        p.y = (a.y > 0.0f) ? __expf(x - emax) : 0.0f;
        x   = si + s.z; x = (x > 0.0f) ? x : ALPHA * x;
        p.z = (a.z > 0.0f) ? __expf(x - emax) : 0.0f;
        x   = si + s.w; x = (x > 0.0f) ? x : ALPHA * x;
        p.w = (a.w > 0.0f) ? __expf(x - emax) : 0.0f;
        sum += p.x + p.y + p.z + p.w;
        sh4[v] = p;
    }
#pragma unroll
    for (int off = 16; off > 0; off >>= 1)
        sum += __shfl_down_sync(0xffffffffu, sum, off);
    __syncthreads();                       // red[] reuse
    if ((tid & 31) == 0) red[tid >> 5] = sum;
    __syncthreads();
    if (tid == 0) {
        float ss = 0.0f;
        int nw = T >> 5;
        for (int w = 0; w < nw; w++) ss += red[w];
        red[32] = 1.0f / ss;
    }
    __syncthreads();
    float inv = red[32];

    // Pass 3: normalized write-out
    for (int v = tid; v < n4; v += T) {
        float4 p = sh4[v];
        p.x *= inv; p.y *= inv; p.z *= inv; p.w *= inv;
        out4[v] = p;
    }
}

// ---------------- launcher ----------------
extern "C" void kernel_launch(void* const* d_in, const int* in_sizes, int n_in,
                              void* d_out, int out_size) {
    const float* h     = (const float*)d_in[0];   // [N, IN_F]
    const float* adj   = (const float*)d_in[1];   // [N, N]
    const float* W     = (const float*)d_in[2];   // [OUT_F, IN_F]
    const float* a_vec = (const float*)d_in[3];   // [2*OUT_F]

    int OUTF = in_sizes[3] / 2;                   // 256
    int INF  = in_sizes[2] / OUTF;                // 512
    int N    = in_sizes[0] / INF;                 // 8192

    float *Wt, *Wh, *ssrc, *sdst, *attn_fb;
    cudaGetSymbolAddress((void**)&Wt,      g_Wt);
    cudaGetSymbolAddress((void**)&Wh,      g_Wh);
    cudaGetSymbolAddress((void**)&ssrc,    g_ssrc);
    cudaGetSymbolAddress((void**)&sdst,    g_sdst);
    cudaGetSymbolAddress((void**)&attn_fb, g_attn_fb);

    float* h_prime = (float*)d_out;
    long long need = (long long)N * OUTF + (long long)N * N;
    float* attn = ((long long)out_size >= need) ? (h_prime + (size_t)N * OUTF) : attn_fb;

    // 1) W transpose
    int nW = INF * OUTF;
    transpose_w<<<(nW + 255) / 256, 256>>>(W, Wt, INF, OUTF);

    // 2) Wh = h @ W^T   (M=N, N=OUTF, K=INF)
    dim3 blk(256);
    dim3 g1(OUTF / 64, N / 128);
    sgemm128x64<<<g1, blk>>>(h, Wt, Wh, N, OUTF, INF);

    // 3) s_src, s_dst
    compute_s<<<N, 256>>>(Wh, a_vec, ssrc, sdst, OUTF);

    // 4) masked softmax -> attention
    size_t shBytes = (size_t)N * sizeof(float) + 64 * sizeof(float);
    attn_softmax<<<N, 256, shBytes>>>(adj, sdst, ssrc, attn, N);

    // 5) h_prime = attention @ Wh  (M=N, N=OUTF, K=N)
    dim3 g2(OUTF / 64, N / 128);
    sgemm128x64<<<g2, blk>>>(attn, Wh, h_prime, N, OUTF, N);
}

// round 4
// speedup vs baseline: 2.2262x; 2.2262x over previous
#include <cuda_runtime.h>
#include <cuda_bf16.h>
#include <float.h>
#include <cstdint>

#define ALPHA 0.2f

// ---------------- static device scratch (no runtime allocation) ----------------
__device__ __align__(16) float g_Wh[8192 * 256];              // Wh [N, OUT_F] fp32
__device__ __align__(16) __nv_bfloat16 g_Whi[256 * 512];      // W hi bf16 [OUT_F, IN_F]
__device__ __align__(16) __nv_bfloat16 g_Wlo[256 * 512];      // W lo bf16
__device__ __align__(16) __nv_bfloat16 g_WhT_hi[256 * 8192];  // Wh^T hi bf16 [OUT_F, N]
__device__ __align__(16) __nv_bfloat16 g_WhT_lo[256 * 8192];  // Wh^T lo bf16
__device__ __align__(16) float g_ssrc[8192];
__device__ __align__(16) float g_sdst[8192];
__device__ __align__(16) float g_attn_fb[67108864];           // fallback attention

// ==================== PTX helpers (portable sm_80+ subset) ====================
__device__ __forceinline__ uint32_t smem_u32(const void* p) {
    uint32_t a;
    asm("{ .reg .u64 t; cvta.to.shared.u64 t, %1; cvt.u32.u64 %0, t; }" : "=r"(a) : "l"(p));
    return a;
}
__device__ __forceinline__ void cp16(uint32_t dst, const void* src) {
    asm volatile("cp.async.cg.shared.global [%0], [%1], 16;" :: "r"(dst), "l"(src) : "memory");
}
__device__ __forceinline__ void cp_commit() {
    asm volatile("cp.async.commit_group;" ::: "memory");
}
__device__ __forceinline__ void cp_wait0() {
    asm volatile("cp.async.wait_group 0;" ::: "memory");
}
__device__ __forceinline__ void ldsm_x4(uint32_t* r, uint32_t addr) {
    asm volatile("ldmatrix.sync.aligned.m8n8.x4.shared.b16 {%0,%1,%2,%3}, [%4];"
                 : "=r"(r[0]), "=r"(r[1]), "=r"(r[2]), "=r"(r[3]) : "r"(addr));
}
// B tiles are stored [n][k] (k contiguous): the m16n8k16 B-fragment wants
// consecutive-k at fixed n per thread, which is plain (non-trans) ldmatrix.
__device__ __forceinline__ void ldsm_x2(uint32_t* r, uint32_t addr) {
    asm volatile("ldmatrix.sync.aligned.m8n8.x2.shared.b16 {%0,%1}, [%2];"
                 : "=r"(r[0]), "=r"(r[1]) : "r"(addr));
}
__device__ __forceinline__ void mma16816(float* c, const uint32_t* a, const uint32_t* b) {
    asm volatile("mma.sync.aligned.m16n8k16.row.col.f32.bf16.bf16.f32 "
                 "{%0,%1,%2,%3}, {%4,%5,%6,%7}, {%8,%9}, {%0,%1,%2,%3};"
                 : "+f"(c[0]), "+f"(c[1]), "+f"(c[2]), "+f"(c[3])
                 : "r"(a[0]), "r"(a[1]), "r"(a[2]), "r"(a[3]), "r"(b[0]), "r"(b[1]));
}
__device__ __forceinline__ void sts_v2(uint32_t addr, uint32_t x, uint32_t y) {
    asm volatile("st.shared.v2.b32 [%0], {%1,%2};" :: "r"(addr), "r"(x), "r"(y) : "memory");
}
__device__ __forceinline__ uint32_t split2(float x, float y, uint32_t& lo) {
    __nv_bfloat16 hx = __float2bfloat16(x);
    __nv_bfloat16 hy = __float2bfloat16(y);
    __nv_bfloat16 lx = __float2bfloat16(x - __bfloat162float(hx));
    __nv_bfloat16 ly = __float2bfloat16(y - __bfloat162float(hy));
    lo = (uint32_t)__bfloat16_as_ushort(lx) | ((uint32_t)__bfloat16_as_ushort(ly) << 16);
    return (uint32_t)__bfloat16_as_ushort(hx) | ((uint32_t)__bfloat16_as_ushort(hy) << 16);
}

// ==================== bf16-split mma.sync GEMM ====================
// C[M,256] = A[M,K] (fp32) @ B^T where Bhi/Blo are bf16 [256][K] row-major
// (B[n][k] = logical Bmat[k][n]). CTA tile 128x128x32, 8 warps (warp tile
// 32x64), double-buffered smem, cp.async for B, LDG+split+STS for A.
// 3 products: Ahi*Bhi + Ahi*Blo + Alo*Bhi.
#define ROWB   80                                // padded row stride (bytes): 32 bf16 + 16B skew
#define TILEB  (128 * ROWB)                      // 10240 B per tile
#define STAGEB (4 * TILEB)                       // Ahi|Alo|Bhi|Blo
#define GEMM_DSMEM (2 * STAGEB)                  // 81920 B

__global__ __launch_bounds__(256, 1)
void mma_gemm(const float* __restrict__ A, const __nv_bfloat16* __restrict__ Bhi,
              const __nv_bfloat16* __restrict__ Blo, float* __restrict__ C,
              int lda, int ldb, int niter) {
    extern __shared__ __align__(128) char dsm[];
    const uint32_t sb = smem_u32(dsm);

    const int tid   = threadIdx.x;
    const int wid   = tid >> 5;
    const int lane  = tid & 31;
    const int warpM = wid & 3;                    // 4 x 32 rows
    const int warpN = wid >> 2;                   // 2 x 64 cols
    const int mBase = blockIdx.x * 128;
    const int colBase = blockIdx.y * 128;

    float acc[2][8][4];
#pragma unroll
    for (int mt = 0; mt < 2; mt++)
#pragma unroll
        for (int nt = 0; nt < 8; nt++)
#pragma unroll
            for (int q = 0; q < 4; q++) acc[mt][nt][q] = 0.0f;

    float4 areg[4];

    // ---- helpers as lambdas ----
    auto ldgA = [&](int it) {
#pragma unroll
        for (int t = 0; t < 4; t++) {
            const int c = tid + t * 256;          // 1024 float4 chunks
            const int row = c >> 3;
            const int seg = c & 7;
            areg[t] = *(const float4*)(A + (size_t)(mBase + row) * lda + it * 32 + seg * 4);
        }
    };
    auto stsA = [&](int s) {
        const uint32_t ahi = sb + s * STAGEB;
        const uint32_t alo = ahi + TILEB;
#pragma unroll
        for (int t = 0; t < 4; t++) {
            const int c = tid + t * 256;
            const int row = c >> 3;
            const int seg = c & 7;
            const uint32_t off = row * ROWB + seg * 8;
            uint32_t l0, l1;
            uint32_t h0 = split2(areg[t].x, areg[t].y, l0);
            uint32_t h1 = split2(areg[t].z, areg[t].w, l1);
            sts_v2(ahi + off, h0, h1);
            sts_v2(alo + off, l0, l1);
        }
    };
    auto loadB = [&](int it, int s) {
        const uint32_t bhi = sb + s * STAGEB + 2 * TILEB;
        const uint32_t blo = bhi + TILEB;
#pragma unroll
        for (int t = 0; t < 4; t++) {
            int c = tid + t * 256;                // 1024 chunks of 16B (512 hi + 512 lo)
            const __nv_bfloat16* src;
            uint32_t dst;
            if (c < 512) {
                const int row = c >> 2, seg = c & 3;
                src = Bhi + (size_t)(colBase + row) * ldb + it * 32 + seg * 8;
                dst = bhi + row * ROWB + seg * 16;
            } else {
                c -= 512;
                const int row = c >> 2, seg = c & 3;
                src = Blo + (size_t)(colBase + row) * ldb + it * 32 + seg * 8;
                dst = blo + row * ROWB + seg * 16;
            }
            cp16(dst, src);
        }
    };
    auto compute = [&](int s) {
        const uint32_t ahi = sb + s * STAGEB;
        const uint32_t alo = ahi + TILEB;
        const uint32_t bhi = ahi + 2 * TILEB;
        const uint32_t blo = ahi + 3 * TILEB;
        const uint32_t arow = (uint32_t)(warpM * 32 + (lane & 15)) * ROWB;
        const uint32_t brow = (uint32_t)(warpN * 64 + (lane & 7)) * ROWB;
#pragma unroll
        for (int ks = 0; ks < 2; ks++) {
            const uint32_t acol = (uint32_t)(ks * 16 + (lane >> 4) * 8) * 2;
            const uint32_t bcol = (uint32_t)(ks * 16 + ((lane >> 3) & 1) * 8) * 2;
            uint32_t ah[2][4], al[2][4];
            ldsm_x4(ah[0], ahi + arow + acol);
            ldsm_x4(ah[1], ahi + arow + 16 * ROWB + acol);
            ldsm_x4(al[0], alo + arow + acol);
            ldsm_x4(al[1], alo + arow + 16 * ROWB + acol);
#pragma unroll
            for (int nt = 0; nt < 8; nt++) {
                uint32_t bh[2], bl[2];
                ldsm_x2(bh, bhi + brow + nt * 8 * ROWB + bcol);
                ldsm_x2(bl, blo + brow + nt * 8 * ROWB + bcol);
#pragma unroll
                for (int mt = 0; mt < 2; mt++) {
                    mma16816(acc[mt][nt], ah[mt], bh);
                    mma16816(acc[mt][nt], ah[mt], bl);
                    mma16816(acc[mt][nt], al[mt], bh);
                }
            }
        }
    };

    // ---- prologue: stage 0 ----
    loadB(0, 0);
    cp_commit();
    ldgA(0);
    stsA(0);
    cp_wait0();
    __syncthreads();

    // ---- main loop ----
    for (int it = 0; it < niter; it++) {
        const int cur = it & 1;
        const bool more = (it + 1) < niter;
        if (more) {
            loadB(it + 1, cur ^ 1);
            cp_commit();
            ldgA(it + 1);
        }
        compute(cur);
        if (more) {
            stsA(cur ^ 1);
            cp_wait0();
        }
        __syncthreads();
    }

    // ---- epilogue ----
#pragma unroll
    for (int mt = 0; mt < 2; mt++) {
        const int r0 = mBase + warpM * 32 + mt * 16 + (lane >> 2);
#pragma unroll
        for (int nt = 0; nt < 8; nt++) {
            const int col = colBase + warpN * 64 + nt * 8 + (lane & 3) * 2;
            float2 v0 = make_float2(acc[mt][nt][0], acc[mt][nt][1]);
            float2 v1 = make_float2(acc[mt][nt][2], acc[mt][nt][3]);
            *(float2*)(C + (size_t)r0 * 256 + col) = v0;
            *(float2*)(C + (size_t)(r0 + 8) * 256 + col) = v1;
        }
    }
}

// ---------------- prep: W -> bf16 hi/lo split ----------------
__global__ void prep_w_split(const float* __restrict__ W, __nv_bfloat16* __restrict__ hi,
                             __nv_bfloat16* __restrict__ lo, int n) {
    int i = blockIdx.x * blockDim.x + threadIdx.x;
    if (i >= n) return;
    float x = W[i];
    __nv_bfloat16 bh = __float2bfloat16(x);
    hi[i] = bh;
    lo[i] = __float2bfloat16(x - __bfloat162float(bh));
}

// ---------------- prep: Wh [M,256] -> WhT hi/lo bf16 [256, M] ----------------
__global__ void prep_whT_split(const float* __restrict__ Wh, __nv_bfloat16* __restrict__ hi,
                               __nv_bfloat16* __restrict__ lo, int M) {
    __shared__ float t[32][33];
    t[threadIdx.y][threadIdx.x] = Wh[(size_t)(blockIdx.x * 32 + threadIdx.y) * 256 +
                                     blockIdx.y * 32 + threadIdx.x];
    __syncthreads();
    float x = t[threadIdx.x][threadIdx.y];
    int on = blockIdx.y * 32 + threadIdx.y;
    int om = blockIdx.x * 32 + threadIdx.x;
    __nv_bfloat16 bh = __float2bfloat16(x);
    hi[(size_t)on * M + om] = bh;
    lo[(size_t)on * M + om] = __float2bfloat16(x - __bfloat162float(bh));
}

// ---------------- s_src / s_dst ----------------
__global__ void compute_s(const float* __restrict__ Wh, const float* __restrict__ a_vec,
                          float* __restrict__ ssrc, float* __restrict__ sdst, int OUTF) {
    int i = blockIdx.x;
    int tid = threadIdx.x;
    float p1 = 0.0f, p2 = 0.0f;
    for (int j = tid; j < OUTF; j += blockDim.x) {
        float v = Wh[(size_t)i * OUTF + j];
        p1 += v * a_vec[j];
        p2 += v * a_vec[OUTF + j];
    }
#pragma unroll
    for (int off = 16; off > 0; off >>= 1) {
        p1 += __shfl_down_sync(0xffffffffu, p1, off);
        p2 += __shfl_down_sync(0xffffffffu, p2, off);
    }
    __shared__ float r1[8], r2[8];
    int wid = tid >> 5;
    if ((tid & 31) == 0) { r1[wid] = p1; r2[wid] = p2; }
    __syncthreads();
    if (tid == 0) {
        float s1 = 0.0f, s2 = 0.0f;
        int nw = blockDim.x >> 5;
        for (int w = 0; w < nw; w++) { s1 += r1[w]; s2 += r2[w]; }
        ssrc[i] = s1;
        sdst[i] = s2;
    }
}

// ---------------- masked row softmax ----------------
__global__ void attn_softmax(const float* __restrict__ adj, const float* __restrict__ sdst,
                             const float* __restrict__ ssrc, float* __restrict__ attn,
                             int Nn) {
    extern __shared__ float sh[];
    float* red = sh + Nn;
    int i = blockIdx.x;
    int tid = threadIdx.x;
    int T = blockDim.x;
    int n4 = Nn >> 2;

    const float4* adj4 = (const float4*)(adj + (size_t)i * Nn);
    const float4* sd4 = (const float4*)sdst;
    float4* sh4 = (float4*)sh;
    float si = ssrc[i];

    float m = -FLT_MAX;
    for (int v = tid; v < n4; v += T) {
        float4 a = adj4[v];
        float4 s = sd4[v];
        sh4[v] = a;
        if (a.x > 0.0f) m = fmaxf(m, s.x);
        if (a.y > 0.0f) m = fmaxf(m, s.y);
        if (a.z > 0.0f) m = fmaxf(m, s.z);
        if (a.w > 0.0f) m = fmaxf(m, s.w);
    }
#pragma unroll
    for (int off = 16; off > 0; off >>= 1)
        m = fmaxf(m, __shfl_down_sync(0xffffffffu, m, off));
    if ((tid & 31) == 0) red[tid >> 5] = m;
    __syncthreads();
    if (tid == 0) {
        float mm = red[0];
        int nw = T >> 5;
        for (int w = 1; w < nw; w++) mm = fmaxf(mm, red[w]);
        red[32] = mm;
    }
    __syncthreads();
    float mAll = red[32];

    float4* out4 = (float4*)(attn + (size_t)i * Nn);

    if (mAll == -FLT_MAX) {
        float u = 1.0f / (float)Nn;
        float4 uv = make_float4(u, u, u, u);
        for (int v = tid; v < n4; v += T) out4[v] = uv;
        return;
    }

    float t0 = si + mAll;
    float emax = (t0 > 0.0f) ? t0 : ALPHA * t0;

    float sum = 0.0f;
    for (int v = tid; v < n4; v += T) {
        float4 a = sh4[v];
        float4 s = sd4[v];
        float4 p;
        float x;
        x = si + s.x; x = (x > 0.0f) ? x : ALPHA * x;
        p.x = (a.x > 0.0f) ? __expf(x - emax) : 0.0f;
        x = si + s.y; x = (x > 0.0f) ? x : ALPHA * x;
        p.y = (a.y > 0.0f) ? __expf(x - emax) : 0.0f;
        x = si + s.z; x = (x > 0.0f) ? x : ALPHA * x;
        p.z = (a.z > 0.0f) ? __expf(x - emax) : 0.0f;
        x = si + s.w; x = (x > 0.0f) ? x : ALPHA * x;
        p.w = (a.w > 0.0f) ? __expf(x - emax) : 0.0f;
        sum += p.x + p.y + p.z + p.w;
        sh4[v] = p;
    }
#pragma unroll
    for (int off = 16; off > 0; off >>= 1)
        sum += __shfl_down_sync(0xffffffffu, sum, off);
    __syncthreads();
    if ((tid & 31) == 0) red[tid >> 5] = sum;
    __syncthreads();
    if (tid == 0) {
        float ss = 0.0f;
        int nw = T >> 5;
        for (int w = 0; w < nw; w++) ss += red[w];
        red[32] = 1.0f / ss;
    }
    __syncthreads();
    float inv = red[32];

    for (int v = tid; v < n4; v += T) {
        float4 p = sh4[v];
        p.x *= inv; p.y *= inv; p.z *= inv; p.w *= inv;
        out4[v] = p;
    }
}

// ---------------- launcher ----------------
extern "C" void kernel_launch(void* const* d_in, const int* in_sizes, int n_in,
                              void* d_out, int out_size) {
    const float* h     = (const float*)d_in[0];   // [N, IN_F]
    const float* adj   = (const float*)d_in[1];   // [N, N]
    const float* W     = (const float*)d_in[2];   // [OUT_F, IN_F]
    const float* a_vec = (const float*)d_in[3];   // [2*OUT_F]

    int OUTF = in_sizes[3] / 2;                   // 256
    int INF  = in_sizes[2] / OUTF;                // 512
    int N    = in_sizes[0] / INF;                 // 8192

    float *Wh, *ssrc, *sdst, *attn_fb;
    __nv_bfloat16 *Whi, *Wlo, *WhThi, *WhTlo;
    cudaGetSymbolAddress((void**)&Wh,      g_Wh);
    cudaGetSymbolAddress((void**)&Whi,     g_Whi);
    cudaGetSymbolAddress((void**)&Wlo,     g_Wlo);
    cudaGetSymbolAddress((void**)&WhThi,   g_WhT_hi);
    cudaGetSymbolAddress((void**)&WhTlo,   g_WhT_lo);
    cudaGetSymbolAddress((void**)&ssrc,    g_ssrc);
    cudaGetSymbolAddress((void**)&sdst,    g_sdst);
    cudaGetSymbolAddress((void**)&attn_fb, g_attn_fb);

    float* h_prime = (float*)d_out;
    long long need = (long long)N * OUTF + (long long)N * N;
    float* attn = ((long long)out_size >= need) ? (h_prime + (size_t)N * OUTF) : attn_fb;

    cudaFuncSetAttribute(mma_gemm, cudaFuncAttributeMaxDynamicSharedMemorySize, GEMM_DSMEM);

    // 1) W -> bf16 hi/lo ([OUT_F, IN_F] row-major == B's [n][k] layout)
    int nW = OUTF * INF;
    prep_w_split<<<(nW + 255) / 256, 256>>>(W, Whi, Wlo, nW);

    // 2) Wh = h @ W^T   (M=N, K=INF, niter=INF/32)
    mma_gemm<<<dim3(N / 128, OUTF / 128), 256, GEMM_DSMEM>>>(h, Whi, Wlo, Wh, INF, INF, INF / 32);

    // 3) s_src, s_dst
    compute_s<<<N, 256>>>(Wh, a_vec, ssrc, sdst, OUTF);

    // 4) Wh -> WhT hi/lo bf16 [OUT_F, N]  (B's [n][k] layout for GEMM-2)
    prep_whT_split<<<dim3(N / 32, OUTF / 32), dim3(32, 32)>>>(Wh, WhThi, WhTlo, N);

    // 5) masked softmax -> attention (fp32, exact output)
    size_t shBytes = (size_t)N * sizeof(float) + 64 * sizeof(float);
    attn_softmax<<<N, 256, shBytes>>>(adj, sdst, ssrc, attn, N);

    // 6) h_prime = attention @ Wh   (M=N, K=N, niter=N/32)
    mma_gemm<<<dim3(N / 128, OUTF / 128), 256, GEMM_DSMEM>>>(attn, WhThi, WhTlo, h_prime, N, N, N / 32);
}

// round 5
// speedup vs baseline: 2.3319x; 1.0475x over previous
#include <cuda_runtime.h>
#include <cuda_bf16.h>
#include <float.h>
#include <cstdint>

#define ALPHA 0.2f

// ---------------- static device scratch (no runtime allocation) ----------------
__device__ __align__(16) float g_Wh[8192 * 256];              // Wh [N, OUT_F] fp32
__device__ __align__(16) __nv_bfloat16 g_Whi[256 * 512];      // W hi bf16 [OUT_F, IN_F]
__device__ __align__(16) __nv_bfloat16 g_Wlo[256 * 512];      // W lo
__device__ __align__(16) __nv_bfloat16 g_hhi[8192 * 512];     // h hi bf16
__device__ __align__(16) __nv_bfloat16 g_hlo[8192 * 512];     // h lo
__device__ __align__(16) __nv_bfloat16 g_WhT_hi[256 * 8192];  // Wh^T hi bf16 [OUT_F, N]
__device__ __align__(16) __nv_bfloat16 g_WhT_lo[256 * 8192];  // Wh^T lo
__device__ __align__(16) __nv_bfloat16 g_attn_hi[8192ull * 8192]; // attention hi bf16
__device__ __align__(16) __nv_bfloat16 g_attn_lo[8192ull * 8192]; // attention lo bf16
__device__ __align__(16) float g_ssrc[8192];
__device__ __align__(16) float g_sdst[8192];
__device__ __align__(16) float g_attn_fb[67108864];           // fallback fp32 attention

// ==================== PTX helpers (portable sm_80+ subset) ====================
__device__ __forceinline__ uint32_t smem_u32(const void* p) {
    uint32_t a;
    asm("{ .reg .u64 t; cvta.to.shared.u64 t, %1; cvt.u32.u64 %0, t; }" : "=r"(a) : "l"(p));
    return a;
}
__device__ __forceinline__ void cp16(uint32_t dst, const void* src) {
    asm volatile("cp.async.cg.shared.global [%0], [%1], 16;" :: "r"(dst), "l"(src) : "memory");
}
__device__ __forceinline__ void cp_commit() {
    asm volatile("cp.async.commit_group;" ::: "memory");
}
__device__ __forceinline__ void cp_wait2() {
    asm volatile("cp.async.wait_group 2;" ::: "memory");
}
__device__ __forceinline__ void ldsm_x4(uint32_t* r, uint32_t addr) {
    asm volatile("ldmatrix.sync.aligned.m8n8.x4.shared.b16 {%0,%1,%2,%3}, [%4];"
                 : "=r"(r[0]), "=r"(r[1]), "=r"(r[2]), "=r"(r[3]) : "r"(addr));
}
__device__ __forceinline__ void mma16816(float* c, const uint32_t* a, const uint32_t* b) {
    asm volatile("mma.sync.aligned.m16n8k16.row.col.f32.bf16.bf16.f32 "
                 "{%0,%1,%2,%3}, {%4,%5,%6,%7}, {%8,%9}, {%0,%1,%2,%3};"
                 : "+f"(c[0]), "+f"(c[1]), "+f"(c[2]), "+f"(c[3])
                 : "r"(a[0]), "r"(a[1]), "r"(a[2]), "r"(a[3]), "r"(b[0]), "r"(b[1]));
}

// ==================== bf16-split mma.sync GEMM (all-bf16 operands) ====================
// C[M,256] = (Ahi+Alo)[M,K] @ (Bhi+Blo)^T, B stored [256][K] row-major.
// CTA tile 128x128x32, 8 warps (warp tile 32x64), 4-stage cp.async pipeline.
// 3 products: Ahi*Bhi + Ahi*Blo + Alo*Bhi.
#define ROWB   80                                // 32 bf16 (64B) + 16B skew
#define TILEB  (128 * ROWB)                      // 10240 B
#define STAGEB (4 * TILEB)                       // Ahi|Alo|Bhi|Blo = 40960 B
#define NSTAGE 4
#define GEMM_DSMEM (NSTAGE * STAGEB)             // 163840 B

__global__ __launch_bounds__(256, 1)
void mma_gemm(const __nv_bfloat16* __restrict__ Ahi, const __nv_bfloat16* __restrict__ Alo,
              const __nv_bfloat16* __restrict__ Bhi, const __nv_bfloat16* __restrict__ Blo,
              float* __restrict__ C, int K, int niter) {
    extern __shared__ __align__(128) char dsm[];
    const uint32_t sb = smem_u32(dsm);

    const int tid   = threadIdx.x;
    const int wid   = tid >> 5;
    const int lane  = tid & 31;
    const int warpM = wid & 3;                    // 4 x 32 rows
    const int warpN = wid >> 2;                   // 2 x 64 cols
    const int mBase = blockIdx.x * 128;
    const int colBase = blockIdx.y * 128;

    float acc[2][8][4];
#pragma unroll
    for (int mt = 0; mt < 2; mt++)
#pragma unroll
        for (int nt = 0; nt < 8; nt++)
#pragma unroll
            for (int q = 0; q < 4; q++) acc[mt][nt][q] = 0.0f;

    auto loadStage = [&](int s, int it) {
        const uint32_t st = sb + s * STAGEB;
#pragma unroll
        for (int t = 0; t < 8; t++) {
            const int c = tid + t * 256;          // 0..2047 16B chunks
            const int tile = c >> 9;              // 0:Ahi 1:Alo 2:Bhi 3:Blo
            const int r = (c >> 2) & 127;
            const int seg = c & 3;
            const __nv_bfloat16* base = (tile == 0) ? Ahi : (tile == 1) ? Alo
                                       : (tile == 2) ? Bhi : Blo;
            const int rowg = (tile < 2) ? (mBase + r) : (colBase + r);
            cp16(st + tile * TILEB + r * ROWB + seg * 16,
                 base + (size_t)rowg * K + it * 32 + seg * 8);
        }
    };

    // A ldsm addr: lanes 0-15 -> rows m0-15, lane>>4 -> k-half
    const uint32_t a_off = (uint32_t)(warpM * 32 + (lane & 15)) * ROWB + (lane >> 4) * 16;
    // B ldsm x4 addr: m0=(n grp, k0) m1=(n grp, k8) m2=(n+8, k0) m3=(n+8, k8)
    const uint32_t b_off = (uint32_t)(warpN * 64 + ((lane >> 4) & 1) * 8 + (lane & 7)) * ROWB
                         + ((lane >> 3) & 1) * 16;

    auto compute = [&](int s) {
        const uint32_t ahi = sb + s * STAGEB;
        const uint32_t alo = ahi + TILEB;
        const uint32_t bhi = ahi + 2 * TILEB;
        const uint32_t blo = ahi + 3 * TILEB;
#pragma unroll
        for (int ks = 0; ks < 2; ks++) {
            uint32_t ah[2][4], al[2][4];
            ldsm_x4(ah[0], ahi + a_off + ks * 32);
            ldsm_x4(ah[1], ahi + a_off + 16 * ROWB + ks * 32);
            ldsm_x4(al[0], alo + a_off + ks * 32);
            ldsm_x4(al[1], alo + a_off + 16 * ROWB + ks * 32);
#pragma unroll
            for (int p = 0; p < 4; p++) {         // nt = 2p, 2p+1
                uint32_t bh[4], bl[4];
                ldsm_x4(bh, bhi + b_off + p * 16 * ROWB + ks * 32);
                ldsm_x4(bl, blo + b_off + p * 16 * ROWB + ks * 32);
#pragma unroll
                for (int mt = 0; mt < 2; mt++) {
                    mma16816(acc[mt][2 * p],     ah[mt], bh + 0);
                    mma16816(acc[mt][2 * p],     ah[mt], bl + 0);
                    mma16816(acc[mt][2 * p],     al[mt], bh + 0);
                    mma16816(acc[mt][2 * p + 1], ah[mt], bh + 2);
                    mma16816(acc[mt][2 * p + 1], ah[mt], bl + 2);
                    mma16816(acc[mt][2 * p + 1], al[mt], bh + 2);
                }
            }
        }
    };

    // ---- prologue: fill 3 stages ----
#pragma unroll
    for (int s = 0; s < NSTAGE - 1; s++) {
        if (s < niter) loadStage(s, s);
        cp_commit();
    }

    // ---- main loop ----
    for (int it = 0; it < niter; it++) {
        cp_wait2();
        __syncthreads();
        if (it + NSTAGE - 1 < niter) loadStage((it + NSTAGE - 1) & (NSTAGE - 1), it + NSTAGE - 1);
        cp_commit();
        compute(it & (NSTAGE - 1));
    }

    // ---- epilogue ----
#pragma unroll
    for (int mt = 0; mt < 2; mt++) {
        const int r0 = mBase + warpM * 32 + mt * 16 + (lane >> 2);
#pragma unroll
        for (int nt = 0; nt < 8; nt++) {
            const int col = colBase + warpN * 64 + nt * 8 + (lane & 3) * 2;
            *(float2*)(C + (size_t)r0 * 256 + col) = make_float2(acc[mt][nt][0], acc[mt][nt][1]);
            *(float2*)(C + (size_t)(r0 + 8) * 256 + col) = make_float2(acc[mt][nt][2], acc[mt][nt][3]);
        }
    }
}

// ---------------- prep: fp32 -> bf16 hi/lo split (elementwise, any array) ----------------
__global__ void prep_split(const float* __restrict__ X, __nv_bfloat16* __restrict__ hi,
                           __nv_bfloat16* __restrict__ lo, int n4) {
    int i = blockIdx.x * blockDim.x + threadIdx.x;
    if (i >= n4) return;
    float4 v = ((const float4*)X)[i];
    __nv_bfloat16 h0 = __float2bfloat16(v.x), h1 = __float2bfloat16(v.y);
    __nv_bfloat16 h2 = __float2bfloat16(v.z), h3 = __float2bfloat16(v.w);
    uint32_t hp0 = (uint32_t)__bfloat16_as_ushort(h0) | ((uint32_t)__bfloat16_as_ushort(h1) << 16);
    uint32_t hp1 = (uint32_t)__bfloat16_as_ushort(h2) | ((uint32_t)__bfloat16_as_ushort(h3) << 16);
    __nv_bfloat16 l0 = __float2bfloat16(v.x - __bfloat162float(h0));
    __nv_bfloat16 l1 = __float2bfloat16(v.y - __bfloat162float(h1));
    __nv_bfloat16 l2 = __float2bfloat16(v.z - __bfloat162float(h2));
    __nv_bfloat16 l3 = __float2bfloat16(v.w - __bfloat162float(h3));
    uint32_t lp0 = (uint32_t)__bfloat16_as_ushort(l0) | ((uint32_t)__bfloat16_as_ushort(l1) << 16);
    uint32_t lp1 = (uint32_t)__bfloat16_as_ushort(l2) | ((uint32_t)__bfloat16_as_ushort(l3) << 16);
    ((uint2*)hi)[i] = make_uint2(hp0, hp1);
    ((uint2*)lo)[i] = make_uint2(lp0, lp1);
}

// ---------------- prep: Wh [M,256] -> WhT hi/lo bf16 [256, M] ----------------
__global__ void prep_whT_split(const float* __restrict__ Wh, __nv_bfloat16* __restrict__ hi,
                               __nv_bfloat16* __restrict__ lo, int M) {
    __shared__ float t[32][33];
    t[threadIdx.y][threadIdx.x] = Wh[(size_t)(blockIdx.x * 32 + threadIdx.y) * 256 +
                                     blockIdx.y * 32 + threadIdx.x];
    __syncthreads();
    float x = t[threadIdx.x][threadIdx.y];
    int on = blockIdx.y * 32 + threadIdx.y;
    int om = blockIdx.x * 32 + threadIdx.x;
    __nv_bfloat16 bh = __float2bfloat16(x);
    hi[(size_t)on * M + om] = bh;
    lo[(size_t)on * M + om] = __float2bfloat16(x - __bfloat162float(bh));
}

// ---------------- s_src / s_dst ----------------
__global__ void compute_s(const float* __restrict__ Wh, const float* __restrict__ a_vec,
                          float* __restrict__ ssrc, float* __restrict__ sdst, int OUTF) {
    int i = blockIdx.x;
    int tid = threadIdx.x;
    float p1 = 0.0f, p2 = 0.0f;
    for (int j = tid; j < OUTF; j += blockDim.x) {
        float v = Wh[(size_t)i * OUTF + j];
        p1 += v * a_vec[j];
        p2 += v * a_vec[OUTF + j];
    }
#pragma unroll
    for (int off = 16; off > 0; off >>= 1) {
        p1 += __shfl_down_sync(0xffffffffu, p1, off);
        p2 += __shfl_down_sync(0xffffffffu, p2, off);
    }
    __shared__ float r1[8], r2[8];
    int wid = tid >> 5;
    if ((tid & 31) == 0) { r1[wid] = p1; r2[wid] = p2; }
    __syncthreads();
    if (tid == 0) {
        float s1 = 0.0f, s2 = 0.0f;
        int nw = blockDim.x >> 5;
        for (int w = 0; w < nw; w++) { s1 += r1[w]; s2 += r2[w]; }
        ssrc[i] = s1;
        sdst[i] = s2;
    }
}

// ---------------- masked row softmax (2-pass, no max needed: scores bounded) ----------------
// Writes fp32 attention + bf16 hi/lo splits for the downstream GEMM.
__global__ __launch_bounds__(512)
void attn_softmax(const float* __restrict__ adj, const float* __restrict__ sdst,
                  const float* __restrict__ ssrc, float* __restrict__ attn,
                  __nv_bfloat16* __restrict__ athi, __nv_bfloat16* __restrict__ atlo,
                  int Nn) {
    extern __shared__ float sh[];                 // [Nn] p-row, then red[]
    float* red = sh + Nn;
    const int i = blockIdx.x;
    const int tid = threadIdx.x;
    const int T = blockDim.x;
    const int n4 = Nn >> 2;

    const float4* adj4 = (const float4*)(adj + (size_t)i * Nn);
    const float4* sd4 = (const float4*)sdst;
    float4* sh4 = (float4*)sh;
    const float si = ssrc[i];

    // Pass 1: exp(leakyrelu(si+sj)) masked, into smem; accumulate sum
    float sum = 0.0f;
    for (int v = tid; v < n4; v += T) {
        float4 a = adj4[v];
        float4 s = sd4[v];
        float4 p;
        float x;
        x = si + s.x; x = (x > 0.0f) ? x : ALPHA * x;
        p.x = (a.x > 0.0f) ? __expf(x) : 0.0f;
        x = si + s.y; x = (x > 0.0f) ? x : ALPHA * x;
        p.y = (a.y > 0.0f) ? __expf(x) : 0.0f;
        x = si + s.z; x = (x > 0.0f) ? x : ALPHA * x;
        p.z = (a.z > 0.0f) ? __expf(x) : 0.0f;
        x = si + s.w; x = (x > 0.0f) ? x : ALPHA * x;
        p.w = (a.w > 0.0f) ? __expf(x) : 0.0f;
        sum += p.x + p.y + p.z + p.w;
        sh4[v] = p;
    }
#pragma unroll
    for (int off = 16; off > 0; off >>= 1)
        sum += __shfl_down_sync(0xffffffffu, sum, off);
    if ((tid & 31) == 0) red[tid >> 5] = sum;
    __syncthreads();
    if (tid == 0) {
        float ss = 0.0f;
        int nw = T >> 5;
        for (int w = 0; w < nw; w++) ss += red[w];
        red[32] = ss;
    }
    __syncthreads();
    const float total = red[32];

    float4* out4 = (float4*)(attn + (size_t)i * Nn);
    uint2* hi2 = (uint2*)(athi + (size_t)i * Nn);
    uint2* lo2 = (uint2*)(atlo + (size_t)i * Nn);

    const bool empty = (total == 0.0f);
    const float inv = empty ? (1.0f / (float)Nn) : (1.0f / total);

    // Pass 2: normalize, write fp32 + bf16 hi/lo
    for (int v = tid; v < n4; v += T) {
        float4 p;
        if (empty) {
            p = make_float4(inv, inv, inv, inv);  // softmax over all -9e15 = uniform
        } else {
            p = sh4[v];
            p.x *= inv; p.y *= inv; p.z *= inv; p.w *= inv;
        }
        out4[v] = p;
        __nv_bfloat16 h0 = __float2bfloat16(p.x), h1 = __float2bfloat16(p.y);
        __nv_bfloat16 h2 = __float2bfloat16(p.z), h3 = __float2bfloat16(p.w);
        hi2[v] = make_uint2(
            (uint32_t)__bfloat16_as_ushort(h0) | ((uint32_t)__bfloat16_as_ushort(h1) << 16),
            (uint32_t)__bfloat16_as_ushort(h2) | ((uint32_t)__bfloat16_as_ushort(h3) << 16));
        __nv_bfloat16 l0 = __float2bfloat16(p.x - __bfloat162float(h0));
        __nv_bfloat16 l1 = __float2bfloat16(p.y - __bfloat162float(h1));
        __nv_bfloat16 l2 = __float2bfloat16(p.z - __bfloat162float(h2));
        __nv_bfloat16 l3 = __float2bfloat16(p.w - __bfloat162float(h3));
        lo2[v] = make_uint2(
            (uint32_t)__bfloat16_as_ushort(l0) | ((uint32_t)__bfloat16_as_ushort(l1) << 16),
            (uint32_t)__bfloat16_as_ushort(l2) | ((uint32_t)__bfloat16_as_ushort(l3) << 16));
    }
}

// ---------------- launcher ----------------
extern "C" void kernel_launch(void* const* d_in, const int* in_sizes, int n_in,
                              void* d_out, int out_size) {
    const float* h     = (const float*)d_in[0];   // [N, IN_F]
    const float* adj   = (const float*)d_in[1];   // [N, N]
    const float* W     = (const float*)d_in[2];   // [OUT_F, IN_F]
    const float* a_vec = (const float*)d_in[3];   // [2*OUT_F]

    int OUTF = in_sizes[3] / 2;                   // 256
    int INF  = in_sizes[2] / OUTF;                // 512
    int N    = in_sizes[0] / INF;                 // 8192

    float *Wh, *ssrc, *sdst, *attn_fb;
    __nv_bfloat16 *Whi, *Wlo, *hhi, *hlo, *WhThi, *WhTlo, *athi, *atlo;
    cudaGetSymbolAddress((void**)&Wh,      g_Wh);
    cudaGetSymbolAddress((void**)&Whi,     g_Whi);
    cudaGetSymbolAddress((void**)&Wlo,     g_Wlo);
    cudaGetSymbolAddress((void**)&hhi,     g_hhi);
    cudaGetSymbolAddress((void**)&hlo,     g_hlo);
    cudaGetSymbolAddress((void**)&WhThi,   g_WhT_hi);
    cudaGetSymbolAddress((void**)&WhTlo,   g_WhT_lo);
    cudaGetSymbolAddress((void**)&athi,    g_attn_hi);
    cudaGetSymbolAddress((void**)&atlo,    g_attn_lo);
    cudaGetSymbolAddress((void**)&ssrc,    g_ssrc);
    cudaGetSymbolAddress((void**)&sdst,    g_sdst);
    cudaGetSymbolAddress((void**)&attn_fb, g_attn_fb);

    float* h_prime = (float*)d_out;
    long long need = (long long)N * OUTF + (long long)N * N;
    float* attn = ((long long)out_size >= need) ? (h_prime + (size_t)N * OUTF) : attn_fb;

    cudaFuncSetAttribute(mma_gemm, cudaFuncAttributeMaxDynamicSharedMemorySize, GEMM_DSMEM);

    // 1) splits: W and h -> bf16 hi/lo
    prep_split<<<(OUTF * INF / 4 + 255) / 256, 256>>>(W, Whi, Wlo, OUTF * INF / 4);
    prep_split<<<(N * INF / 4 + 255) / 256, 256>>>(h, hhi, hlo, N * INF / 4);

    // 2) Wh = h @ W^T   (K=INF, niter=INF/32)
    mma_gemm<<<dim3(N / 128, OUTF / 128), 256, GEMM_DSMEM>>>(hhi, hlo, Whi, Wlo, Wh, INF, INF / 32);

    // 3) s_src, s_dst
    compute_s<<<N, 256>>>(Wh, a_vec, ssrc, sdst, OUTF);

    // 4) Wh -> WhT hi/lo bf16 [OUT_F, N]
    prep_whT_split<<<dim3(N / 32, OUTF / 32), dim3(32, 32)>>>(Wh, WhThi, WhTlo, N);

    // 5) masked softmax -> attention fp32 + bf16 hi/lo
    size_t shBytes = (size_t)N * sizeof(float) + 64 * sizeof(float);
    attn_softmax<<<N, 512, shBytes>>>(adj, sdst, ssrc, attn, athi, atlo, N);

    // 6) h_prime = attention @ Wh   (K=N, niter=N/32)
    mma_gemm<<<dim3(N / 128, OUTF / 128), 256, GEMM_DSMEM>>>(athi, atlo, WhThi, WhTlo, h_prime, N, N / 32);
}

// round 6
// speedup vs baseline: 3.0907x; 1.3254x over previous
#include <cuda_runtime.h>
#include <cuda_fp16.h>
#include <float.h>
#include <cstdint>

#define ALPHA 0.2f

// ---------------- static device scratch (no runtime allocation) ----------------
__device__ __align__(16) float g_Wh[8192 * 256];            // Wh [N, OUT_F] fp32
__device__ __align__(16) __half g_Whi[256 * 512];           // W hi fp16 [OUT_F, IN_F]
__device__ __align__(16) __half g_Wlo[256 * 512];           // W lo
__device__ __align__(16) __half g_hhi[8192 * 512];          // h hi fp16
__device__ __align__(16) __half g_hlo[8192 * 512];          // h lo
__device__ __align__(16) __half g_WhT_hi[256 * 8192];       // Wh^T hi fp16 [OUT_F, N]
__device__ __align__(16) __half g_WhT_lo[256 * 8192];       // Wh^T lo
__device__ __align__(16) __half g_attn_h[8192ull * 8192];   // attention fp16 (single)
__device__ __align__(16) float g_ssrc[8192];
__device__ __align__(16) float g_sdst[8192];
__device__ __align__(16) float g_attn_fb[67108864];         // fallback fp32 attention

// ==================== PTX helpers (portable sm_80+ subset) ====================
__device__ __forceinline__ uint32_t smem_u32(const void* p) {
    uint32_t a;
    asm("{ .reg .u64 t; cvta.to.shared.u64 t, %1; cvt.u32.u64 %0, t; }" : "=r"(a) : "l"(p));
    return a;
}
__device__ __forceinline__ void cp16(uint32_t dst, const void* src) {
    asm volatile("cp.async.cg.shared.global [%0], [%1], 16;" :: "r"(dst), "l"(src) : "memory");
}
__device__ __forceinline__ void cp_commit() {
    asm volatile("cp.async.commit_group;" ::: "memory");
}
__device__ __forceinline__ void cp_wait2() {
    asm volatile("cp.async.wait_group 2;" ::: "memory");
}
__device__ __forceinline__ void ldsm_x4(uint32_t* r, uint32_t addr) {
    asm volatile("ldmatrix.sync.aligned.m8n8.x4.shared.b16 {%0,%1,%2,%3}, [%4];"
                 : "=r"(r[0]), "=r"(r[1]), "=r"(r[2]), "=r"(r[3]) : "r"(addr));
}
__device__ __forceinline__ void mma16816(float* c, const uint32_t* a, const uint32_t* b) {
    asm volatile("mma.sync.aligned.m16n8k16.row.col.f32.f16.f16.f32 "
                 "{%0,%1,%2,%3}, {%4,%5,%6,%7}, {%8,%9}, {%0,%1,%2,%3};"
                 : "+f"(c[0]), "+f"(c[1]), "+f"(c[2]), "+f"(c[3])
                 : "r"(a[0]), "r"(a[1]), "r"(a[2]), "r"(a[3]), "r"(b[0]), "r"(b[1]));
}

// ==================== fp16-split mma.sync GEMM ====================
// C[M,256] = A[M,K] @ B^T, B stored [256][K] row-major (B[n][k]).
// SPLIT_A=true : 3 products  Ahi*Bhi + Ahi*Blo + Alo*Bhi  (GEMM-1, high acc)
// SPLIT_A=false: 2 products  A*Bhi + A*Blo                (GEMM-2, A=attention fp16)
// CTA tile 128x128x32, 8 warps (warp tile 32x64), 4-stage cp.async pipeline.
#define ROWB   80                                // 32 fp16 (64B) + 16B skew
#define TILEB  (128 * ROWB)                      // 10240 B
#define NSTAGE 4

template <bool SPLIT_A>
__global__ __launch_bounds__(256, 1)
void mma_gemm(const __half* __restrict__ Ahi, const __half* __restrict__ Alo,
              const __half* __restrict__ Bhi, const __half* __restrict__ Blo,
              float* __restrict__ C, int K, int niter) {
    constexpr int NTILE  = SPLIT_A ? 4 : 3;      // Ahi[,Alo],Bhi,Blo
    constexpr int STAGEB = NTILE * TILEB;
    extern __shared__ __align__(128) char dsm[];
    const uint32_t sb = smem_u32(dsm);

    const int tid   = threadIdx.x;
    const int wid   = tid >> 5;
    const int lane  = tid & 31;
    const int warpM = wid & 3;                    // 4 x 32 rows
    const int warpN = wid >> 2;                   // 2 x 64 cols
    const int mBase = blockIdx.x * 128;
    const int colBase = blockIdx.y * 128;

    float acc[2][8][4];
#pragma unroll
    for (int mt = 0; mt < 2; mt++)
#pragma unroll
        for (int nt = 0; nt < 8; nt++)
#pragma unroll
            for (int q = 0; q < 4; q++) acc[mt][nt][q] = 0.0f;

    auto loadStage = [&](int s, int it) {
        const uint32_t st = sb + s * STAGEB;
        constexpr int NCH = NTILE * 512;          // 16B chunks per stage
#pragma unroll
        for (int t = 0; t < NCH / 256; t++) {
            const int c = tid + t * 256;
            const int tile = c >> 9;
            const int r = (c >> 2) & 127;
            const int seg = c & 3;
            const __half* base;
            bool isA;
            if (SPLIT_A) {
                base = (tile == 0) ? Ahi : (tile == 1) ? Alo : (tile == 2) ? Bhi : Blo;
                isA = tile < 2;
            } else {
                base = (tile == 0) ? Ahi : (tile == 1) ? Bhi : Blo;
                isA = tile == 0;
            }
            const int rowg = isA ? (mBase + r) : (colBase + r);
            cp16(st + tile * TILEB + r * ROWB + seg * 16,
                 base + (size_t)rowg * K + it * 32 + seg * 8);
        }
    };

    // A ldsm addr: lanes 0-15 -> rows m0-15, lane>>4 -> k-half
    const uint32_t a_off = (uint32_t)(warpM * 32 + (lane & 15)) * ROWB + (lane >> 4) * 16;
    // B ldsm x4 addr
    const uint32_t b_off = (uint32_t)(warpN * 64 + ((lane >> 4) & 1) * 8 + (lane & 7)) * ROWB
                         + ((lane >> 3) & 1) * 16;

    auto compute = [&](int s) {
        const uint32_t ahi = sb + s * STAGEB;
        const uint32_t alo = ahi + TILEB;                       // valid iff SPLIT_A
        const uint32_t bhi = ahi + (SPLIT_A ? 2 : 1) * TILEB;
        const uint32_t blo = bhi + TILEB;
#pragma unroll
        for (int ks = 0; ks < 2; ks++) {
            uint32_t ah[2][4], al[2][4];
            ldsm_x4(ah[0], ahi + a_off + ks * 32);
            ldsm_x4(ah[1], ahi + a_off + 16 * ROWB + ks * 32);
            if (SPLIT_A) {
                ldsm_x4(al[0], alo + a_off + ks * 32);
                ldsm_x4(al[1], alo + a_off + 16 * ROWB + ks * 32);
            }
#pragma unroll
            for (int p = 0; p < 4; p++) {         // nt = 2p, 2p+1
                uint32_t bh[4], bl[4];
                ldsm_x4(bh, bhi + b_off + p * 16 * ROWB + ks * 32);
                ldsm_x4(bl, blo + b_off + p * 16 * ROWB + ks * 32);
#pragma unroll
                for (int mt = 0; mt < 2; mt++) {
                    mma16816(acc[mt][2 * p],     ah[mt], bh + 0);
                    mma16816(acc[mt][2 * p],     ah[mt], bl + 0);
                    mma16816(acc[mt][2 * p + 1], ah[mt], bh + 2);
                    mma16816(acc[mt][2 * p + 1], ah[mt], bl + 2);
                    if (SPLIT_A) {
                        mma16816(acc[mt][2 * p],     al[mt], bh + 0);
                        mma16816(acc[mt][2 * p + 1], al[mt], bh + 2);
                    }
                }
            }
        }
    };

    // ---- prologue: fill 3 stages ----
#pragma unroll
    for (int s = 0; s < NSTAGE - 1; s++) {
        if (s < niter) loadStage(s, s);
        cp_commit();
    }

    // ---- main loop ----
    for (int it = 0; it < niter; it++) {
        cp_wait2();
        __syncthreads();
        if (it + NSTAGE - 1 < niter) loadStage((it + NSTAGE - 1) & (NSTAGE - 1), it + NSTAGE - 1);
        cp_commit();
        compute(it & (NSTAGE - 1));
    }

    // ---- epilogue ----
#pragma unroll
    for (int mt = 0; mt < 2; mt++) {
        const int r0 = mBase + warpM * 32 + mt * 16 + (lane >> 2);
#pragma unroll
        for (int nt = 0; nt < 8; nt++) {
            const int col = colBase + warpN * 64 + nt * 8 + (lane & 3) * 2;
            *(float2*)(C + (size_t)r0 * 256 + col) = make_float2(acc[mt][nt][0], acc[mt][nt][1]);
            *(float2*)(C + (size_t)(r0 + 8) * 256 + col) = make_float2(acc[mt][nt][2], acc[mt][nt][3]);
        }
    }
}

// ---------------- prep: fp32 -> fp16 hi/lo split ----------------
__global__ void prep_split(const float* __restrict__ X, __half* __restrict__ hi,
                           __half* __restrict__ lo, int n4) {
    int i = blockIdx.x * blockDim.x + threadIdx.x;
    if (i >= n4) return;
    float4 v = ((const float4*)X)[i];
    __half h0 = __float2half_rn(v.x), h1 = __float2half_rn(v.y);
    __half h2 = __float2half_rn(v.z), h3 = __float2half_rn(v.w);
    __half l0 = __float2half_rn(v.x - __half2float(h0));
    __half l1 = __float2half_rn(v.y - __half2float(h1));
    __half l2 = __float2half_rn(v.z - __half2float(h2));
    __half l3 = __float2half_rn(v.w - __half2float(h3));
    ((uint2*)hi)[i] = make_uint2(
        (uint32_t)__half_as_ushort(h0) | ((uint32_t)__half_as_ushort(h1) << 16),
        (uint32_t)__half_as_ushort(h2) | ((uint32_t)__half_as_ushort(h3) << 16));
    ((uint2*)lo)[i] = make_uint2(
        (uint32_t)__half_as_ushort(l0) | ((uint32_t)__half_as_ushort(l1) << 16),
        (uint32_t)__half_as_ushort(l2) | ((uint32_t)__half_as_ushort(l3) << 16));
}

// ---------------- prep: Wh [M,256] -> WhT hi/lo fp16 [256, M] ----------------
__global__ void prep_whT_split(const float* __restrict__ Wh, __half* __restrict__ hi,
                               __half* __restrict__ lo, int M) {
    __shared__ float t[32][33];
    t[threadIdx.y][threadIdx.x] = Wh[(size_t)(blockIdx.x * 32 + threadIdx.y) * 256 +
                                     blockIdx.y * 32 + threadIdx.x];
    __syncthreads();
    float x = t[threadIdx.x][threadIdx.y];
    int on = blockIdx.y * 32 + threadIdx.y;
    int om = blockIdx.x * 32 + threadIdx.x;
    __half bh = __float2half_rn(x);
    hi[(size_t)on * M + om] = bh;
    lo[(size_t)on * M + om] = __float2half_rn(x - __half2float(bh));
}

// ---------------- s_src / s_dst ----------------
__global__ void compute_s(const float* __restrict__ Wh, const float* __restrict__ a_vec,
                          float* __restrict__ ssrc, float* __restrict__ sdst, int OUTF) {
    int i = blockIdx.x;
    int tid = threadIdx.x;
    float p1 = 0.0f, p2 = 0.0f;
    for (int j = tid; j < OUTF; j += blockDim.x) {
        float v = Wh[(size_t)i * OUTF + j];
        p1 += v * a_vec[j];
        p2 += v * a_vec[OUTF + j];
    }
#pragma unroll
    for (int off = 16; off > 0; off >>= 1) {
        p1 += __shfl_down_sync(0xffffffffu, p1, off);
        p2 += __shfl_down_sync(0xffffffffu, p2, off);
    }
    __shared__ float r1[8], r2[8];
    int wid = tid >> 5;
    if ((tid & 31) == 0) { r1[wid] = p1; r2[wid] = p2; }
    __syncthreads();
    if (tid == 0) {
        float s1 = 0.0f, s2 = 0.0f;
        int nw = blockDim.x >> 5;
        for (int w = 0; w < nw; w++) { s1 += r1[w]; s2 += r2[w]; }
        ssrc[i] = s1;
        sdst[i] = s2;
    }
}

// ---------------- masked row softmax (2-pass) ----------------
// Writes fp32 attention + single fp16 copy for the downstream GEMM.
__global__ __launch_bounds__(512)
void attn_softmax(const float* __restrict__ adj, const float* __restrict__ sdst,
                  const float* __restrict__ ssrc, float* __restrict__ attn,
                  __half* __restrict__ atth, int Nn) {
    extern __shared__ float sh[];                 // [Nn] p-row, then red[]
    float* red = sh + Nn;
    const int i = blockIdx.x;
    const int tid = threadIdx.x;
    const int T = blockDim.x;
    const int n4 = Nn >> 2;

    const float4* adj4 = (const float4*)(adj + (size_t)i * Nn);
    const float4* sd4 = (const float4*)sdst;
    float4* sh4 = (float4*)sh;
    const float si = ssrc[i];

    // Pass 1: masked exp(leakyrelu(si+sj)) into smem; accumulate sum
    float sum = 0.0f;
    for (int v = tid; v < n4; v += T) {
        float4 a = adj4[v];
        float4 s = sd4[v];
        float4 p;
        float x;
        x = si + s.x; x = (x > 0.0f) ? x : ALPHA * x;
        p.x = (a.x > 0.0f) ? __expf(x) : 0.0f;
        x = si + s.y; x = (x > 0.0f) ? x : ALPHA * x;
        p.y = (a.y > 0.0f) ? __expf(x) : 0.0f;
        x = si + s.z; x = (x > 0.0f) ? x : ALPHA * x;
        p.z = (a.z > 0.0f) ? __expf(x) : 0.0f;
        x = si + s.w; x = (x > 0.0f) ? x : ALPHA * x;
        p.w = (a.w > 0.0f) ? __expf(x) : 0.0f;
        sum += p.x + p.y + p.z + p.w;
        sh4[v] = p;
    }
#pragma unroll
    for (int off = 16; off > 0; off >>= 1)
        sum += __shfl_down_sync(0xffffffffu, sum, off);
    if ((tid & 31) == 0) red[tid >> 5] = sum;
    __syncthreads();
    if (tid == 0) {
        float ss = 0.0f;
        int nw = T >> 5;
        for (int w = 0; w < nw; w++) ss += red[w];
        red[32] = ss;
    }
    __syncthreads();
    const float total = red[32];

    float4* out4 = (float4*)(attn + (size_t)i * Nn);
    uint2* h2 = (uint2*)(atth + (size_t)i * Nn);

    const bool empty = (total == 0.0f);
    const float inv = empty ? (1.0f / (float)Nn) : (1.0f / total);

    // Pass 2: normalize, write fp32 + fp16
    for (int v = tid; v < n4; v += T) {
        float4 p;
        if (empty) {
            p = make_float4(inv, inv, inv, inv);  // softmax over all -9e15 = uniform
        } else {
            p = sh4[v];
            p.x *= inv; p.y *= inv; p.z *= inv; p.w *= inv;
        }
        out4[v] = p;
        __half q0 = __float2half_rn(p.x), q1 = __float2half_rn(p.y);
        __half q2 = __float2half_rn(p.z), q3 = __float2half_rn(p.w);
        h2[v] = make_uint2(
            (uint32_t)__half_as_ushort(q0) | ((uint32_t)__half_as_ushort(q1) << 16),
            (uint32_t)__half_as_ushort(q2) | ((uint32_t)__half_as_ushort(q3) << 16));
    }
}

// ---------------- launcher ----------------
extern "C" void kernel_launch(void* const* d_in, const int* in_sizes, int n_in,
                              void* d_out, int out_size) {
    const float* h     = (const float*)d_in[0];   // [N, IN_F]
    const float* adj   = (const float*)d_in[1];   // [N, N]
    const float* W     = (const float*)d_in[2];   // [OUT_F, IN_F]
    const float* a_vec = (const float*)d_in[3];   // [2*OUT_F]

    int OUTF = in_sizes[3] / 2;                   // 256
    int INF  = in_sizes[2] / OUTF;                // 512
    int N    = in_sizes[0] / INF;                 // 8192

    float *Wh, *ssrc, *sdst, *attn_fb;
    __half *Whi, *Wlo, *hhi, *hlo, *WhThi, *WhTlo, *atth;
    cudaGetSymbolAddress((void**)&Wh,      g_Wh);
    cudaGetSymbolAddress((void**)&Whi,     g_Whi);
    cudaGetSymbolAddress((void**)&Wlo,     g_Wlo);
    cudaGetSymbolAddress((void**)&hhi,     g_hhi);
    cudaGetSymbolAddress((void**)&hlo,     g_hlo);
    cudaGetSymbolAddress((void**)&WhThi,   g_WhT_hi);
    cudaGetSymbolAddress((void**)&WhTlo,   g_WhT_lo);
    cudaGetSymbolAddress((void**)&atth,    g_attn_h);
    cudaGetSymbolAddress((void**)&ssrc,    g_ssrc);
    cudaGetSymbolAddress((void**)&sdst,    g_sdst);
    cudaGetSymbolAddress((void**)&attn_fb, g_attn_fb);

    float* h_prime = (float*)d_out;
    long long need = (long long)N * OUTF + (long long)N * N;
    float* attn = ((long long)out_size >= need) ? (h_prime + (size_t)N * OUTF) : attn_fb;

    const int DS3 = NSTAGE * 4 * TILEB;           // SPLIT_A=true
    const int DS2 = NSTAGE * 3 * TILEB;           // SPLIT_A=false
    cudaFuncSetAttribute(mma_gemm<true>,  cudaFuncAttributeMaxDynamicSharedMemorySize, DS3);
    cudaFuncSetAttribute(mma_gemm<false>, cudaFuncAttributeMaxDynamicSharedMemorySize, DS2);

    // 1) splits: W and h -> fp16 hi/lo
    prep_split<<<(OUTF * INF / 4 + 255) / 256, 256>>>(W, Whi, Wlo, OUTF * INF / 4);
    prep_split<<<(N * INF / 4 + 255) / 256, 256>>>(h, hhi, hlo, N * INF / 4);

    // 2) Wh = h @ W^T   (3-product fp16, K=INF)
    mma_gemm<true><<<dim3(N / 128, OUTF / 128), 256, DS3>>>(hhi, hlo, Whi, Wlo, Wh, INF, INF / 32);

    // 3) s_src, s_dst
    compute_s<<<N, 256>>>(Wh, a_vec, ssrc, sdst, OUTF);

    // 4) Wh -> WhT hi/lo fp16 [OUT_F, N]
    prep_whT_split<<<dim3(N / 32, OUTF / 32), dim3(32, 32)>>>(Wh, WhThi, WhTlo, N);

    // 5) masked softmax -> attention fp32 + fp16
    size_t shBytes = (size_t)N * sizeof(float) + 64 * sizeof(float);
    attn_softmax<<<N, 512, shBytes>>>(adj, sdst, ssrc, attn, atth, N);

    // 6) h_prime = attention @ Wh   (2-product fp16: A single, B split; K=N)
    mma_gemm<false><<<dim3(N / 128, OUTF / 128), 256, DS2>>>(atth, nullptr, WhThi, WhTlo,
                                                             h_prime, N, N / 32);
}

// round 7
// speedup vs baseline: 3.9137x; 1.2663x over previous
#include <cuda_runtime.h>
#include <cuda_fp16.h>
#include <float.h>
#include <cstdint>

#define ALPHA 0.2f

// ---------------- static device scratch (no runtime allocation) ----------------
__device__ __align__(16) float g_Wh[8192 * 256];            // Wh [N, OUT_F] fp32
__device__ __align__(16) __half g_Whi[256 * 512];           // W hi fp16 [OUT_F, IN_F]
__device__ __align__(16) __half g_Wlo[256 * 512];           // W lo
__device__ __align__(16) __half g_hhi[8192 * 512];          // h hi fp16
__device__ __align__(16) __half g_hlo[8192 * 512];          // h lo
__device__ __align__(16) __half g_WhT_hi[256 * 8192];       // Wh^T fp16 [OUT_F, N]
__device__ __align__(16) __half g_attn_h[8192ull * 8192];   // attention fp16 (single)
__device__ __align__(16) float g_ssrc[8192];
__device__ __align__(16) float g_sdst[8192];
__device__ __align__(16) float g_attn_fb[67108864];         // fallback fp32 attention

// ==================== PTX helpers (portable sm_80+ subset) ====================
__device__ __forceinline__ uint32_t smem_u32(const void* p) {
    uint32_t a;
    asm("{ .reg .u64 t; cvta.to.shared.u64 t, %1; cvt.u32.u64 %0, t; }" : "=r"(a) : "l"(p));
    return a;
}
__device__ __forceinline__ void cp16(uint32_t dst, const void* src) {
    asm volatile("cp.async.cg.shared.global [%0], [%1], 16;" :: "r"(dst), "l"(src) : "memory");
}
__device__ __forceinline__ void cp_commit() {
    asm volatile("cp.async.commit_group;" ::: "memory");
}
template <int Ngrp>
__device__ __forceinline__ void cp_wait() {
    asm volatile("cp.async.wait_group %0;" :: "n"(Ngrp) : "memory");
}
__device__ __forceinline__ void ldsm_x4(uint32_t* r, uint32_t addr) {
    asm volatile("ldmatrix.sync.aligned.m8n8.x4.shared.b16 {%0,%1,%2,%3}, [%4];"
                 : "=r"(r[0]), "=r"(r[1]), "=r"(r[2]), "=r"(r[3]) : "r"(addr));
}
__device__ __forceinline__ void mma16816(float* c, const uint32_t* a, const uint32_t* b) {
    asm volatile("mma.sync.aligned.m16n8k16.row.col.f32.f16.f16.f32 "
                 "{%0,%1,%2,%3}, {%4,%5,%6,%7}, {%8,%9}, {%0,%1,%2,%3};"
                 : "+f"(c[0]), "+f"(c[1]), "+f"(c[2]), "+f"(c[3])
                 : "r"(a[0]), "r"(a[1]), "r"(a[2]), "r"(a[3]), "r"(b[0]), "r"(b[1]));
}

// ==================== fp16 mma.sync GEMM ====================
// C[M,256] = A[M,K] @ B^T, B stored [256][K] row-major (B[n][k]).
// SPLIT=true : 4 tiles (Ahi,Alo,Bhi,Blo), 3 products, 4 stages  (GEMM-1, high acc)
// SPLIT=false: 2 tiles (A,B),             1 product,  8 stages  (GEMM-2)
// CTA tile 128x128x32, 8 warps (warp tile 32x64), cp.async pipeline.
#define ROWB   80                                // 32 fp16 (64B) + 16B skew
#define TILEB  (128 * ROWB)                      // 10240 B

template <bool SPLIT>
__global__ __launch_bounds__(256, 1)
void mma_gemm(const __half* __restrict__ Ahi, const __half* __restrict__ Alo,
              const __half* __restrict__ Bhi, const __half* __restrict__ Blo,
              float* __restrict__ C, int K, int niter) {
    constexpr int NTILE  = SPLIT ? 4 : 2;
    constexpr int NSTAGE = SPLIT ? 4 : 8;        // both powers of 2
    constexpr int STAGEB = NTILE * TILEB;
    extern __shared__ __align__(128) char dsm[];
    const uint32_t sb = smem_u32(dsm);

    const int tid   = threadIdx.x;
    const int wid   = tid >> 5;
    const int lane  = tid & 31;
    const int warpM = wid & 3;                    // 4 x 32 rows
    const int warpN = wid >> 2;                   // 2 x 64 cols
    const int mBase = blockIdx.x * 128;
    const int colBase = blockIdx.y * 128;

    float acc[2][8][4];
#pragma unroll
    for (int mt = 0; mt < 2; mt++)
#pragma unroll
        for (int nt = 0; nt < 8; nt++)
#pragma unroll
            for (int q = 0; q < 4; q++) acc[mt][nt][q] = 0.0f;

    auto loadStage = [&](int s, int it) {
        const uint32_t st = sb + s * STAGEB;
        constexpr int NCH = NTILE * 512;          // 16B chunks per stage
#pragma unroll
        for (int t = 0; t < NCH / 256; t++) {
            const int c = tid + t * 256;
            const int tile = c >> 9;
            const int r = (c >> 2) & 127;
            const int seg = c & 3;
            const __half* base;
            bool isA;
            if (SPLIT) {
                base = (tile == 0) ? Ahi : (tile == 1) ? Alo : (tile == 2) ? Bhi : Blo;
                isA = tile < 2;
            } else {
                base = (tile == 0) ? Ahi : Bhi;
                isA = tile == 0;
            }
            const int rowg = isA ? (mBase + r) : (colBase + r);
            cp16(st + tile * TILEB + r * ROWB + seg * 16,
                 base + (size_t)rowg * K + it * 32 + seg * 8);
        }
    };

    // A ldsm addr: lanes 0-15 -> rows m0-15, lane>>4 -> k-half
    const uint32_t a_off = (uint32_t)(warpM * 32 + (lane & 15)) * ROWB + (lane >> 4) * 16;
    // B ldsm x4 addr
    const uint32_t b_off = (uint32_t)(warpN * 64 + ((lane >> 4) & 1) * 8 + (lane & 7)) * ROWB
                         + ((lane >> 3) & 1) * 16;

    auto compute = [&](int s) {
        const uint32_t ahi = sb + s * STAGEB;
        const uint32_t alo = ahi + TILEB;                       // valid iff SPLIT
        const uint32_t bhi = ahi + (SPLIT ? 2 : 1) * TILEB;
        const uint32_t blo = bhi + TILEB;                       // valid iff SPLIT
#pragma unroll
        for (int ks = 0; ks < 2; ks++) {
            uint32_t ah[2][4], al[2][4];
            ldsm_x4(ah[0], ahi + a_off + ks * 32);
            ldsm_x4(ah[1], ahi + a_off + 16 * ROWB + ks * 32);
            if (SPLIT) {
                ldsm_x4(al[0], alo + a_off + ks * 32);
                ldsm_x4(al[1], alo + a_off + 16 * ROWB + ks * 32);
            }
#pragma unroll
            for (int p = 0; p < 4; p++) {         // nt = 2p, 2p+1
                uint32_t bh[4];
                ldsm_x4(bh, bhi + b_off + p * 16 * ROWB + ks * 32);
#pragma unroll
                for (int mt = 0; mt < 2; mt++) {
                    mma16816(acc[mt][2 * p],     ah[mt], bh + 0);
                    mma16816(acc[mt][2 * p + 1], ah[mt], bh + 2);
                }
                if (SPLIT) {
                    uint32_t bl[4];
                    ldsm_x4(bl, blo + b_off + p * 16 * ROWB + ks * 32);
#pragma unroll
                    for (int mt = 0; mt < 2; mt++) {
                        mma16816(acc[mt][2 * p],     ah[mt], bl + 0);
                        mma16816(acc[mt][2 * p + 1], ah[mt], bl + 2);
                        mma16816(acc[mt][2 * p],     al[mt], bh + 0);
                        mma16816(acc[mt][2 * p + 1], al[mt], bh + 2);
                    }
                }
            }
        }
    };

    // ---- prologue: fill NSTAGE-1 stages ----
#pragma unroll
    for (int s = 0; s < NSTAGE - 1; s++) {
        if (s < niter) loadStage(s, s);
        cp_commit();
    }

    // ---- main loop ----
    for (int it = 0; it < niter; it++) {
        cp_wait<NSTAGE - 2>();
        __syncthreads();
        if (it + NSTAGE - 1 < niter) loadStage((it + NSTAGE - 1) & (NSTAGE - 1), it + NSTAGE - 1);
        cp_commit();
        compute(it & (NSTAGE - 1));
    }

    // ---- epilogue ----
#pragma unroll
    for (int mt = 0; mt < 2; mt++) {
        const int r0 = mBase + warpM * 32 + mt * 16 + (lane >> 2);
#pragma unroll
        for (int nt = 0; nt < 8; nt++) {
            const int col = colBase + warpN * 64 + nt * 8 + (lane & 3) * 2;
            *(float2*)(C + (size_t)r0 * 256 + col) = make_float2(acc[mt][nt][0], acc[mt][nt][1]);
            *(float2*)(C + (size_t)(r0 + 8) * 256 + col) = make_float2(acc[mt][nt][2], acc[mt][nt][3]);
        }
    }
}

// ---------------- prep: fp32 -> fp16 hi/lo split ----------------
__global__ void prep_split(const float* __restrict__ X, __half* __restrict__ hi,
                           __half* __restrict__ lo, int n4) {
    int i = blockIdx.x * blockDim.x + threadIdx.x;
    if (i >= n4) return;
    float4 v = ((const float4*)X)[i];
    __half h0 = __float2half_rn(v.x), h1 = __float2half_rn(v.y);
    __half h2 = __float2half_rn(v.z), h3 = __float2half_rn(v.w);
    __half l0 = __float2half_rn(v.x - __half2float(h0));
    __half l1 = __float2half_rn(v.y - __half2float(h1));
    __half l2 = __float2half_rn(v.z - __half2float(h2));
    __half l3 = __float2half_rn(v.w - __half2float(h3));
    ((uint2*)hi)[i] = make_uint2(
        (uint32_t)__half_as_ushort(h0) | ((uint32_t)__half_as_ushort(h1) << 16),
        (uint32_t)__half_as_ushort(h2) | ((uint32_t)__half_as_ushort(h3) << 16));
    ((uint2*)lo)[i] = make_uint2(
        (uint32_t)__half_as_ushort(l0) | ((uint32_t)__half_as_ushort(l1) << 16),
        (uint32_t)__half_as_ushort(l2) | ((uint32_t)__half_as_ushort(l3) << 16));
}

// ---------------- prep: Wh [M,256] -> WhT fp16 [256, M] ----------------
__global__ void prep_whT(const float* __restrict__ Wh, __half* __restrict__ hi, int M) {
    __shared__ float t[32][33];
    t[threadIdx.y][threadIdx.x] = Wh[(size_t)(blockIdx.x * 32 + threadIdx.y) * 256 +
                                     blockIdx.y * 32 + threadIdx.x];
    __syncthreads();
    float x = t[threadIdx.x][threadIdx.y];
    int on = blockIdx.y * 32 + threadIdx.y;
    int om = blockIdx.x * 32 + threadIdx.x;
    hi[(size_t)on * M + om] = __float2half_rn(x);
}

// ---------------- s_src / s_dst ----------------
__global__ void compute_s(const float* __restrict__ Wh, const float* __restrict__ a_vec,
                          float* __restrict__ ssrc, float* __restrict__ sdst, int OUTF) {
    int i = blockIdx.x;
    int tid = threadIdx.x;
    float p1 = 0.0f, p2 = 0.0f;
    for (int j = tid; j < OUTF; j += blockDim.x) {
        float v = Wh[(size_t)i * OUTF + j];
        p1 += v * a_vec[j];
        p2 += v * a_vec[OUTF + j];
    }
#pragma unroll
    for (int off = 16; off > 0; off >>= 1) {
        p1 += __shfl_down_sync(0xffffffffu, p1, off);
        p2 += __shfl_down_sync(0xffffffffu, p2, off);
    }
    __shared__ float r1[8], r2[8];
    int wid = tid >> 5;
    if ((tid & 31) == 0) { r1[wid] = p1; r2[wid] = p2; }
    __syncthreads();
    if (tid == 0) {
        float s1 = 0.0f, s2 = 0.0f;
        int nw = blockDim.x >> 5;
        for (int w = 0; w < nw; w++) { s1 += r1[w]; s2 += r2[w]; }
        ssrc[i] = s1;
        sdst[i] = s2;
    }
}

// ---------------- masked row softmax (2-pass) ----------------
// Writes fp32 attention + single fp16 copy for the downstream GEMM.
__global__ __launch_bounds__(512)
void attn_softmax(const float* __restrict__ adj, const float* __restrict__ sdst,
                  const float* __restrict__ ssrc, float* __restrict__ attn,
                  __half* __restrict__ atth, int Nn) {
    extern __shared__ float sh[];                 // [Nn] p-row, then red[]
    float* red = sh + Nn;
    const int i = blockIdx.x;
    const int tid = threadIdx.x;
    const int T = blockDim.x;
    const int n4 = Nn >> 2;

    const float4* adj4 = (const float4*)(adj + (size_t)i * Nn);
    const float4* sd4 = (const float4*)sdst;
    float4* sh4 = (float4*)sh;
    const float si = ssrc[i];

    // Pass 1: masked exp(leakyrelu(si+sj)) into smem; accumulate sum
    float sum = 0.0f;
    for (int v = tid; v < n4; v += T) {
        float4 a = adj4[v];
        float4 s = sd4[v];
        float4 p;
        float x;
        x = si + s.x; x = (x > 0.0f) ? x : ALPHA * x;
        p.x = (a.x > 0.0f) ? __expf(x) : 0.0f;
        x = si + s.y; x = (x > 0.0f) ? x : ALPHA * x;
        p.y = (a.y > 0.0f) ? __expf(x) : 0.0f;
        x = si + s.z; x = (x > 0.0f) ? x : ALPHA * x;
        p.z = (a.z > 0.0f) ? __expf(x) : 0.0f;
        x = si + s.w; x = (x > 0.0f) ? x : ALPHA * x;
        p.w = (a.w > 0.0f) ? __expf(x) : 0.0f;
        sum += p.x + p.y + p.z + p.w;
        sh4[v] = p;
    }
#pragma unroll
    for (int off = 16; off > 0; off >>= 1)
        sum += __shfl_down_sync(0xffffffffu, sum, off);
    if ((tid & 31) == 0) red[tid >> 5] = sum;
    __syncthreads();
    if (tid == 0) {
        float ss = 0.0f;
        int nw = T >> 5;
        for (int w = 0; w < nw; w++) ss += red[w];
        red[32] = ss;
    }
    __syncthreads();
    const float total = red[32];

    float4* out4 = (float4*)(attn + (size_t)i * Nn);
    uint2* h2 = (uint2*)(atth + (size_t)i * Nn);

    const bool empty = (total == 0.0f);
    const float inv = empty ? (1.0f / (float)Nn) : (1.0f / total);

    // Pass 2: normalize, write fp32 + fp16
    for (int v = tid; v < n4; v += T) {
        float4 p;
        if (empty) {
            p = make_float4(inv, inv, inv, inv);  // softmax over all -9e15 = uniform
        } else {
            p = sh4[v];
            p.x *= inv; p.y *= inv; p.z *= inv; p.w *= inv;
        }
        out4[v] = p;
        __half q0 = __float2half_rn(p.x), q1 = __float2half_rn(p.y);
        __half q2 = __float2half_rn(p.z), q3 = __float2half_rn(p.w);
        h2[v] = make_uint2(
            (uint32_t)__half_as_ushort(q0) | ((uint32_t)__half_as_ushort(q1) << 16),
            (uint32_t)__half_as_ushort(q2) | ((uint32_t)__half_as_ushort(q3) << 16));
    }
}

// ---------------- launcher ----------------
extern "C" void kernel_launch(void* const* d_in, const int* in_sizes, int n_in,
                              void* d_out, int out_size) {
    const float* h     = (const float*)d_in[0];   // [N, IN_F]
    const float* adj   = (const float*)d_in[1];   // [N, N]
    const float* W     = (const float*)d_in[2];   // [OUT_F, IN_F]
    const float* a_vec = (const float*)d_in[3];   // [2*OUT_F]

    int OUTF = in_sizes[3] / 2;                   // 256
    int INF  = in_sizes[2] / OUTF;                // 512
    int N    = in_sizes[0] / INF;                 // 8192

    float *Wh, *ssrc, *sdst, *attn_fb;
    __half *Whi, *Wlo, *hhi, *hlo, *WhThi, *atth;
    cudaGetSymbolAddress((void**)&Wh,      g_Wh);
    cudaGetSymbolAddress((void**)&Whi,     g_Whi);
    cudaGetSymbolAddress((void**)&Wlo,     g_Wlo);
    cudaGetSymbolAddress((void**)&hhi,     g_hhi);
    cudaGetSymbolAddress((void**)&hlo,     g_hlo);
    cudaGetSymbolAddress((void**)&WhThi,   g_WhT_hi);
    cudaGetSymbolAddress((void**)&atth,    g_attn_h);
    cudaGetSymbolAddress((void**)&ssrc,    g_ssrc);
    cudaGetSymbolAddress((void**)&sdst,    g_sdst);
    cudaGetSymbolAddress((void**)&attn_fb, g_attn_fb);

    float* h_prime = (float*)d_out;
    long long need = (long long)N * OUTF + (long long)N * N;
    float* attn = ((long long)out_size >= need) ? (h_prime + (size_t)N * OUTF) : attn_fb;

    const int DS3 = 4 * 4 * TILEB;                // SPLIT=true : 4 stages x 4 tiles
    const int DS1 = 8 * 2 * TILEB;                // SPLIT=false: 8 stages x 2 tiles
    cudaFuncSetAttribute(mma_gemm<true>,  cudaFuncAttributeMaxDynamicSharedMemorySize, DS3);
    cudaFuncSetAttribute(mma_gemm<false>, cudaFuncAttributeMaxDynamicSharedMemorySize, DS1);

    // 1) splits: W and h -> fp16 hi/lo
    prep_split<<<(OUTF * INF / 4 + 255) / 256, 256>>>(W, Whi, Wlo, OUTF * INF / 4);
    prep_split<<<(N * INF / 4 + 255) / 256, 256>>>(h, hhi, hlo, N * INF / 4);

    // 2) Wh = h @ W^T   (3-product fp16, K=INF)
    mma_gemm<true><<<dim3(N / 128, OUTF / 128), 256, DS3>>>(hhi, hlo, Whi, Wlo, Wh, INF, INF / 32);

    // 3) s_src, s_dst
    compute_s<<<N, 256>>>(Wh, a_vec, ssrc, sdst, OUTF);

    // 4) Wh -> WhT fp16 [OUT_F, N]
    prep_whT<<<dim3(N / 32, OUTF / 32), dim3(32, 32)>>>(Wh, WhThi, N);

    // 5) masked softmax -> attention fp32 + fp16
    size_t shBytes = (size_t)N * sizeof(float) + 64 * sizeof(float);
    attn_softmax<<<N, 512, shBytes>>>(adj, sdst, ssrc, attn, atth, N);

    // 6) h_prime = attention @ Wh   (single-product fp16; K=N)
    mma_gemm<false><<<dim3(N / 128, OUTF / 128), 256, DS1>>>(atth, nullptr, WhThi, nullptr,
                                                             h_prime, N, N / 32);
}

// round 8
// speedup vs baseline: 4.1532x; 1.0612x over previous
#include <cuda_runtime.h>
#include <cuda_fp16.h>
#include <float.h>
#include <cstdint>

#define ALPHA 0.2f

// ---------------- static device scratch (no runtime allocation) ----------------
__device__ __align__(16) __half g_Whi[256 * 512];           // W hi fp16 [OUT_F, IN_F]
__device__ __align__(16) __half g_Wlo[256 * 512];           // W lo
__device__ __align__(16) __half g_WhT[256 * 8192];          // Wh^T fp16 [OUT_F, N]
__device__ __align__(16) __half g_attn_h[8192ull * 8192];   // attention fp16
__device__ __align__(16) float g_spart[8 * 8192];           // s partials [8 groups][N]
__device__ __align__(16) float g_ssrc[8192];
__device__ __align__(16) float g_sdst[8192];
__device__ __align__(16) float g_attn_fb[67108864];         // fallback fp32 attention

// ==================== PTX helpers (portable sm_80+ subset) ====================
__device__ __forceinline__ uint32_t smem_u32(const void* p) {
    uint32_t a;
    asm("{ .reg .u64 t; cvta.to.shared.u64 t, %1; cvt.u32.u64 %0, t; }" : "=r"(a) : "l"(p));
    return a;
}
__device__ __forceinline__ void cp16(uint32_t dst, const void* src) {
    asm volatile("cp.async.cg.shared.global [%0], [%1], 16;" :: "r"(dst), "l"(src) : "memory");
}
__device__ __forceinline__ void cp_commit() {
    asm volatile("cp.async.commit_group;" ::: "memory");
}
template <int Ngrp>
__device__ __forceinline__ void cp_wait() {
    asm volatile("cp.async.wait_group %0;" :: "n"(Ngrp) : "memory");
}
__device__ __forceinline__ void ldsm_x4(uint32_t* r, uint32_t addr) {
    asm volatile("ldmatrix.sync.aligned.m8n8.x4.shared.b16 {%0,%1,%2,%3}, [%4];"
                 : "=r"(r[0]), "=r"(r[1]), "=r"(r[2]), "=r"(r[3]) : "r"(addr));
}
__device__ __forceinline__ void mma16816(float* c, const uint32_t* a, const uint32_t* b) {
    asm volatile("mma.sync.aligned.m16n8k16.row.col.f32.f16.f16.f32 "
                 "{%0,%1,%2,%3}, {%4,%5,%6,%7}, {%8,%9}, {%0,%1,%2,%3};"
                 : "+f"(c[0]), "+f"(c[1]), "+f"(c[2]), "+f"(c[3])
                 : "r"(a[0]), "r"(a[1]), "r"(a[2]), "r"(a[3]), "r"(b[0]), "r"(b[1]));
}
__device__ __forceinline__ void sts_v2(uint32_t addr, uint32_t x, uint32_t y) {
    asm volatile("st.shared.v2.b32 [%0], {%1,%2};" :: "r"(addr), "r"(x), "r"(y) : "memory");
}
__device__ __forceinline__ uint32_t split2(float x, float y, uint32_t& lo) {
    __half hx = __float2half_rn(x);
    __half hy = __float2half_rn(y);
    __half lx = __float2half_rn(x - __half2float(hx));
    __half ly = __float2half_rn(y - __half2float(hy));
    lo = (uint32_t)__half_as_ushort(lx) | ((uint32_t)__half_as_ushort(ly) << 16);
    return (uint32_t)__half_as_ushort(hx) | ((uint32_t)__half_as_ushort(hy) << 16);
}

#define ROWB   80                                // 32 fp16 (64B) + 16B skew
#define TILEB  (128 * ROWB)                      // 10240 B

// ==================== GEMM-1 fused ====================
// Wh = h @ W^T  (3-product fp16 split, fp32 h split on the fly).
// Epilogue: s_src/s_dst partials from fp32 acc -> g_spart (deterministic),
//           WhT fp16 written transposed via smem.
// CTA tile 128x128x32, 8 warps. B (Whi/Wlo) 4-stage cp.async; A 2-stage LDG/split.
// smem: B stages 4 x 2*TILEB = 81920 | A stages 2 x 2*TILEB = 40960  -> 122880
#define G1_DSMEM (4 * 2 * TILEB + 2 * 2 * TILEB)

__global__ __launch_bounds__(256, 1)
void gemm1_fused(const float* __restrict__ A, const __half* __restrict__ Bhi,
                 const __half* __restrict__ Blo, __half* __restrict__ WhT,
                 float* __restrict__ spart, const float* __restrict__ a_vec,
                 int K, int niter, int M, int OUTF) {
    extern __shared__ __align__(128) char dsm[];
    const uint32_t sb = smem_u32(dsm);

    const int tid   = threadIdx.x;
    const int wid   = tid >> 5;
    const int lane  = tid & 31;
    const int warpM = wid & 3;
    const int warpN = wid >> 2;
    const int mBase = blockIdx.x * 128;
    const int colBase = blockIdx.y * 128;       // within OUT_F

    float acc[2][8][4];
#pragma unroll
    for (int mt = 0; mt < 2; mt++)
#pragma unroll
        for (int nt = 0; nt < 8; nt++)
#pragma unroll
            for (int q = 0; q < 4; q++) acc[mt][nt][q] = 0.0f;

    float4 areg[4];

    auto Bst = [&](int s) { return sb + s * (2 * TILEB); };
    auto Ast = [&](int s) { return sb + 4 * 2 * TILEB + s * (2 * TILEB); };

    auto loadB = [&](int s, int it) {
#pragma unroll
        for (int t = 0; t < 4; t++) {
            const int c = tid + t * 256;          // 1024 chunks: Bhi 512 | Blo 512
            const int tile = c >> 9;
            const int r = (c >> 2) & 127;
            const int seg = c & 3;
            cp16(Bst(s) + tile * TILEB + r * ROWB + seg * 16,
                 (tile ? Blo : Bhi) + (size_t)(colBase + r) * K + it * 32 + seg * 8);
        }
    };
    auto ldgA = [&](int it) {
#pragma unroll
        for (int t = 0; t < 4; t++) {
            const int c = tid + t * 256;
            const int row = c >> 3;
            const int seg = c & 7;
            areg[t] = *(const float4*)(A + (size_t)(mBase + row) * K + it * 32 + seg * 4);
        }
    };
    auto stsA = [&](int s) {
        const uint32_t ahi = Ast(s);
        const uint32_t alo = ahi + TILEB;
#pragma unroll
        for (int t = 0; t < 4; t++) {
            const int c = tid + t * 256;
            const int row = c >> 3;
            const int seg = c & 7;
            const uint32_t off = row * ROWB + seg * 8;
            uint32_t l0, l1;
            uint32_t h0 = split2(areg[t].x, areg[t].y, l0);
            uint32_t h1 = split2(areg[t].z, areg[t].w, l1);
            sts_v2(ahi + off, h0, h1);
            sts_v2(alo + off, l0, l1);
        }
    };

    const uint32_t a_off = (uint32_t)(warpM * 32 + (lane & 15)) * ROWB + (lane >> 4) * 16;
    const uint32_t b_off = (uint32_t)(warpN * 64 + ((lane >> 4) & 1) * 8 + (lane & 7)) * ROWB
                         + ((lane >> 3) & 1) * 16;

    auto compute = [&](int sB, int sA) {
        const uint32_t ahi = Ast(sA);
        const uint32_t alo = ahi + TILEB;
        const uint32_t bhi = Bst(sB);
        const uint32_t blo = bhi + TILEB;
#pragma unroll
        for (int ks = 0; ks < 2; ks++) {
            uint32_t ah[2][4], al[2][4];
            ldsm_x4(ah[0], ahi + a_off + ks * 32);
            ldsm_x4(ah[1], ahi + a_off + 16 * ROWB + ks * 32);
            ldsm_x4(al[0], alo + a_off + ks * 32);
            ldsm_x4(al[1], alo + a_off + 16 * ROWB + ks * 32);
#pragma unroll
            for (int p = 0; p < 4; p++) {
                uint32_t bh[4], bl[4];
                ldsm_x4(bh, bhi + b_off + p * 16 * ROWB + ks * 32);
                ldsm_x4(bl, blo + b_off + p * 16 * ROWB + ks * 32);
#pragma unroll
                for (int mt = 0; mt < 2; mt++) {
                    mma16816(acc[mt][2 * p],     ah[mt], bh + 0);
                    mma16816(acc[mt][2 * p + 1], ah[mt], bh + 2);
                    mma16816(acc[mt][2 * p],     ah[mt], bl + 0);
                    mma16816(acc[mt][2 * p + 1], ah[mt], bl + 2);
                    mma16816(acc[mt][2 * p],     al[mt], bh + 0);
                    mma16816(acc[mt][2 * p + 1], al[mt], bh + 2);
                }
            }
        }
    };

    // ---- prologue ----
    ldgA(0);
    loadB(0, 0); cp_commit();
    if (niter > 1) loadB(1, 1);
    cp_commit();
    if (niter > 2) loadB(2, 2);
    cp_commit();
    stsA(0);

    // ---- main loop ----
    for (int it = 0; it < niter; it++) {
        cp_wait<2>();
        __syncthreads();
        if (it + 3 < niter) loadB((it + 3) & 3, it + 3);
        cp_commit();
        if (it + 1 < niter) ldgA(it + 1);
        compute(it & 3, it & 1);
        if (it + 1 < niter) stsA((it + 1) & 1);
        __syncthreads();
    }

    // ---- epilogue 1: s partials from fp32 acc ----
    {
        float a1v[16], a2v[16];
#pragma unroll
        for (int nt = 0; nt < 8; nt++)
#pragma unroll
            for (int e = 0; e < 2; e++) {
                const int col = colBase + warpN * 64 + nt * 8 + (lane & 3) * 2 + e;
                a1v[nt * 2 + e] = a_vec[col];
                a2v[nt * 2 + e] = a_vec[OUTF + col];
            }
        const int g = (blockIdx.y << 1) | warpN;   // 0..3
#pragma unroll
        for (int mt = 0; mt < 2; mt++)
#pragma unroll
            for (int half = 0; half < 2; half++) {
                float p1 = 0.0f, p2 = 0.0f;
#pragma unroll
                for (int nt = 0; nt < 8; nt++)
#pragma unroll
                    for (int e = 0; e < 2; e++) {
                        const float v = acc[mt][nt][half * 2 + e];
                        p1 += v * a1v[nt * 2 + e];
                        p2 += v * a2v[nt * 2 + e];
                    }
                p1 += __shfl_xor_sync(0xffffffffu, p1, 1);
                p1 += __shfl_xor_sync(0xffffffffu, p1, 2);
                p2 += __shfl_xor_sync(0xffffffffu, p2, 1);
                p2 += __shfl_xor_sync(0xffffffffu, p2, 2);
                if ((lane & 3) == 0) {
                    const int row = mBase + warpM * 32 + mt * 16 + (lane >> 2) + half * 8;
                    spart[g * M + row] = p1;
                    spart[(g + 4) * M + row] = p2;
                }
            }
    }

    // ---- epilogue 2: WhT fp16 transposed via smem ----
    {
        __half* sT = (__half*)dsm;                // [128][136] halfs = 34816 B
        __syncthreads();
#pragma unroll
        for (int mt = 0; mt < 2; mt++)
#pragma unroll
            for (int nt = 0; nt < 8; nt++)
#pragma unroll
                for (int q = 0; q < 4; q++) {
                    const int nl = warpN * 64 + nt * 8 + (lane & 3) * 2 + (q & 1);
                    const int ml = warpM * 32 + mt * 16 + (lane >> 2) + (q >> 1) * 8;
                    sT[nl * 136 + ml] = __float2half_rn(acc[mt][nt][q]);
                }
        __syncthreads();
#pragma unroll
        for (int t = 0; t < 8; t++) {
            const int c = tid + t * 256;          // 2048 chunks of 8 halfs
            const int n = c >> 4;
            const int m8 = (c & 15) * 8;
            uint4 v = *(const uint4*)&sT[n * 136 + m8];
            *(uint4*)&WhT[(size_t)(colBase + n) * M + mBase + m8] = v;
        }
    }
}

// ---------------- combine s partials ----------------
__global__ void combine_s(const float* __restrict__ spart, float* __restrict__ ssrc,
                          float* __restrict__ sdst, int M) {
    int i = blockIdx.x * blockDim.x + threadIdx.x;
    if (i >= M) return;
    ssrc[i] = spart[0 * M + i] + spart[1 * M + i] + spart[2 * M + i] + spart[3 * M + i];
    sdst[i] = spart[4 * M + i] + spart[5 * M + i] + spart[6 * M + i] + spart[7 * M + i];
}

// ==================== GEMM-2: h_prime = attention(fp16) @ WhT^T ====================
// Single fp16 product, 8-stage cp.async pipeline, CTA tile 128x128x32.
#define G2_NSTAGE 8
#define G2_DSMEM  (G2_NSTAGE * 2 * TILEB)        // 163840

__global__ __launch_bounds__(256, 1)
void mma_gemm2(const __half* __restrict__ Ah, const __half* __restrict__ Bh,
               float* __restrict__ C, int K, int niter) {
    extern __shared__ __align__(128) char dsm[];
    const uint32_t sb = smem_u32(dsm);

    const int tid   = threadIdx.x;
    const int wid   = tid >> 5;
    const int lane  = tid & 31;
    const int warpM = wid & 3;
    const int warpN = wid >> 2;
    const int mBase = blockIdx.x * 128;
    const int colBase = blockIdx.y * 128;

    float acc[2][8][4];
#pragma unroll
    for (int mt = 0; mt < 2; mt++)
#pragma unroll
        for (int nt = 0; nt < 8; nt++)
#pragma unroll
            for (int q = 0; q < 4; q++) acc[mt][nt][q] = 0.0f;

    auto loadStage = [&](int s, int it) {
        const uint32_t st = sb + s * (2 * TILEB);
#pragma unroll
        for (int t = 0; t < 4; t++) {
            const int c = tid + t * 256;
            const int tile = c >> 9;              // 0:A 1:B
            const int r = (c >> 2) & 127;
            const int seg = c & 3;
            const __half* base = tile ? Bh : Ah;
            const int rowg = tile ? (colBase + r) : (mBase + r);
            cp16(st + tile * TILEB + r * ROWB + seg * 16,
                 base + (size_t)rowg * K + it * 32 + seg * 8);
        }
    };

    const uint32_t a_off = (uint32_t)(warpM * 32 + (lane & 15)) * ROWB + (lane >> 4) * 16;
    const uint32_t b_off = (uint32_t)(warpN * 64 + ((lane >> 4) & 1) * 8 + (lane & 7)) * ROWB
                         + ((lane >> 3) & 1) * 16;

    auto compute = [&](int s) {
        const uint32_t ahi = sb + s * (2 * TILEB);
        const uint32_t bhi = ahi + TILEB;
#pragma unroll
        for (int ks = 0; ks < 2; ks++) {
            uint32_t ah[2][4];
            ldsm_x4(ah[0], ahi + a_off + ks * 32);
            ldsm_x4(ah[1], ahi + a_off + 16 * ROWB + ks * 32);
#pragma unroll
            for (int p = 0; p < 4; p++) {
                uint32_t bh[4];
                ldsm_x4(bh, bhi + b_off + p * 16 * ROWB + ks * 32);
#pragma unroll
                for (int mt = 0; mt < 2; mt++) {
                    mma16816(acc[mt][2 * p],     ah[mt], bh + 0);
                    mma16816(acc[mt][2 * p + 1], ah[mt], bh + 2);
                }
            }
        }
    };

#pragma unroll
    for (int s = 0; s < G2_NSTAGE - 1; s++) {
        if (s < niter) loadStage(s, s);
        cp_commit();
    }
    for (int it = 0; it < niter; it++) {
        cp_wait<G2_NSTAGE - 2>();
        __syncthreads();
        if (it + G2_NSTAGE - 1 < niter)
            loadStage((it + G2_NSTAGE - 1) & (G2_NSTAGE - 1), it + G2_NSTAGE - 1);
        cp_commit();
        compute(it & (G2_NSTAGE - 1));
    }

#pragma unroll
    for (int mt = 0; mt < 2; mt++) {
        const int r0 = mBase + warpM * 32 + mt * 16 + (lane >> 2);
#pragma unroll
        for (int nt = 0; nt < 8; nt++) {
            const int col = colBase + warpN * 64 + nt * 8 + (lane & 3) * 2;
            *(float2*)(C + (size_t)r0 * 256 + col) = make_float2(acc[mt][nt][0], acc[mt][nt][1]);
            *(float2*)(C + (size_t)(r0 + 8) * 256 + col) = make_float2(acc[mt][nt][2], acc[mt][nt][3]);
        }
    }
}

// ---------------- prep: W fp32 -> fp16 hi/lo ----------------
__global__ void prep_split(const float* __restrict__ X, __half* __restrict__ hi,
                           __half* __restrict__ lo, int n4) {
    int i = blockIdx.x * blockDim.x + threadIdx.x;
    if (i >= n4) return;
    float4 v = ((const float4*)X)[i];
    __half h0 = __float2half_rn(v.x), h1 = __float2half_rn(v.y);
    __half h2 = __float2half_rn(v.z), h3 = __float2half_rn(v.w);
    __half l0 = __float2half_rn(v.x - __half2float(h0));
    __half l1 = __float2half_rn(v.y - __half2float(h1));
    __half l2 = __float2half_rn(v.z - __half2float(h2));
    __half l3 = __float2half_rn(v.w - __half2float(h3));
    ((uint2*)hi)[i] = make_uint2(
        (uint32_t)__half_as_ushort(h0) | ((uint32_t)__half_as_ushort(h1) << 16),
        (uint32_t)__half_as_ushort(h2) | ((uint32_t)__half_as_ushort(h3) << 16));
    ((uint2*)lo)[i] = make_uint2(
        (uint32_t)__half_as_ushort(l0) | ((uint32_t)__half_as_ushort(l1) << 16),
        (uint32_t)__half_as_ushort(l2) | ((uint32_t)__half_as_ushort(l3) << 16));
}

// ---------------- masked row softmax (2-pass) ----------------
__global__ __launch_bounds__(512)
void attn_softmax(const float* __restrict__ adj, const float* __restrict__ sdst,
                  const float* __restrict__ ssrc, float* __restrict__ attn,
                  __half* __restrict__ atth, int Nn) {
    extern __shared__ float sh[];
    float* red = sh + Nn;
    const int i = blockIdx.x;
    const int tid = threadIdx.x;
    const int T = blockDim.x;
    const int n4 = Nn >> 2;

    const float4* adj4 = (const float4*)(adj + (size_t)i * Nn);
    const float4* sd4 = (const float4*)sdst;
    float4* sh4 = (float4*)sh;
    const float si = ssrc[i];

    float sum = 0.0f;
    for (int v = tid; v < n4; v += T) {
        float4 a = adj4[v];
        float4 s = sd4[v];
        float4 p;
        float x;
        x = si + s.x; x = (x > 0.0f) ? x : ALPHA * x;
        p.x = (a.x > 0.0f) ? __expf(x) : 0.0f;
        x = si + s.y; x = (x > 0.0f) ? x : ALPHA * x;
        p.y = (a.y > 0.0f) ? __expf(x) : 0.0f;
        x = si + s.z; x = (x > 0.0f) ? x : ALPHA * x;
        p.z = (a.z > 0.0f) ? __expf(x) : 0.0f;
        x = si + s.w; x = (x > 0.0f) ? x : ALPHA * x;
        p.w = (a.w > 0.0f) ? __expf(x) : 0.0f;
        sum += p.x + p.y + p.z + p.w;
        sh4[v] = p;
    }
#pragma unroll
    for (int off = 16; off > 0; off >>= 1)
        sum += __shfl_down_sync(0xffffffffu, sum, off);
    if ((tid & 31) == 0) red[tid >> 5] = sum;
    __syncthreads();
    if (tid == 0) {
        float ss = 0.0f;
        int nw = T >> 5;
        for (int w = 0; w < nw; w++) ss += red[w];
        red[32] = ss;
    }
    __syncthreads();
    const float total = red[32];

    float4* out4 = (float4*)(attn + (size_t)i * Nn);
    uint2* h2 = (uint2*)(atth + (size_t)i * Nn);

    const bool empty = (total == 0.0f);
    const float inv = empty ? (1.0f / (float)Nn) : (1.0f / total);

    for (int v = tid; v < n4; v += T) {
        float4 p;
        if (empty) {
            p = make_float4(inv, inv, inv, inv);
        } else {
            p = sh4[v];
            p.x *= inv; p.y *= inv; p.z *= inv; p.w *= inv;
        }
        out4[v] = p;
        __half q0 = __float2half_rn(p.x), q1 = __float2half_rn(p.y);
        __half q2 = __float2half_rn(p.z), q3 = __float2half_rn(p.w);
        h2[v] = make_uint2(
            (uint32_t)__half_as_ushort(q0) | ((uint32_t)__half_as_ushort(q1) << 16),
            (uint32_t)__half_as_ushort(q2) | ((uint32_t)__half_as_ushort(q3) << 16));
    }
}

// ---------------- launcher ----------------
extern "C" void kernel_launch(void* const* d_in, const int* in_sizes, int n_in,
                              void* d_out, int out_size) {
    const float* h     = (const float*)d_in[0];   // [N, IN_F]
    const float* adj   = (const float*)d_in[1];   // [N, N]
    const float* W     = (const float*)d_in[2];   // [OUT_F, IN_F]
    const float* a_vec = (const float*)d_in[3];   // [2*OUT_F]

    int OUTF = in_sizes[3] / 2;                   // 256
    int INF  = in_sizes[2] / OUTF;                // 512
    int N    = in_sizes[0] / INF;                 // 8192

    float *spart, *ssrc, *sdst, *attn_fb;
    __half *Whi, *Wlo, *WhT, *atth;
    cudaGetSymbolAddress((void**)&Whi,     g_Whi);
    cudaGetSymbolAddress((void**)&Wlo,     g_Wlo);
    cudaGetSymbolAddress((void**)&WhT,     g_WhT);
    cudaGetSymbolAddress((void**)&atth,    g_attn_h);
    cudaGetSymbolAddress((void**)&spart,   g_spart);
    cudaGetSymbolAddress((void**)&ssrc,    g_ssrc);
    cudaGetSymbolAddress((void**)&sdst,    g_sdst);
    cudaGetSymbolAddress((void**)&attn_fb, g_attn_fb);

    float* h_prime = (float*)d_out;
    long long need = (long long)N * OUTF + (long long)N * N;
    float* attn = ((long long)out_size >= need) ? (h_prime + (size_t)N * OUTF) : attn_fb;

    cudaFuncSetAttribute(gemm1_fused, cudaFuncAttributeMaxDynamicSharedMemorySize, G1_DSMEM);
    cudaFuncSetAttribute(mma_gemm2,   cudaFuncAttributeMaxDynamicSharedMemorySize, G2_DSMEM);

    // 1) W -> fp16 hi/lo
    prep_split<<<(OUTF * INF / 4 + 255) / 256, 256>>>(W, Whi, Wlo, OUTF * INF / 4);

    // 2) fused GEMM-1: WhT fp16 + s partials (Wh fp32 never materialized)
    gemm1_fused<<<dim3(N / 128, OUTF / 128), 256, G1_DSMEM>>>(
        h, Whi, Wlo, WhT, spart, a_vec, INF, INF / 32, N, OUTF);

    // 3) combine s partials
    combine_s<<<(N + 255) / 256, 256>>>(spart, ssrc, sdst, N);

    // 4) masked softmax -> attention fp32 + fp16
    size_t shBytes = (size_t)N * sizeof(float) + 64 * sizeof(float);
    attn_softmax<<<N, 512, shBytes>>>(adj, sdst, ssrc, attn, atth, N);

    // 5) GEMM-2: h_prime = attention @ Wh
    mma_gemm2<<<dim3(N / 128, OUTF / 128), 256, G2_DSMEM>>>(atth, WhT, h_prime, N, N / 32);
}